// round 6
// baseline (speedup 1.0000x reference)
#include <cuda_runtime.h>
#include <math.h>
#include <stdint.h>

// Problem constants (fixed-shape problem)
#define Nn   20000
#define Ee   100000
#define Ll   4
#define Dd   64
#define Hh   8
#define HIDc 512

// mma.sync tf32 LSTM tiling
#define BM   256        // edges per CTA
#define BNH  32         // hidden units per CTA -> 128 gate columns
#define BK   32         // K per chunk
#define LDSW 40         // smem row stride words (32+8 pad: LDS.64 conflict-free)
#define A_WORDS (BM * LDSW)            // 10240
#define B_WORDS (128 * LDSW)           // 5120
#define STAGE_WORDS (A_WORDS + B_WORDS)
#define NSTAGE 3
#define DYN_SMEM (NSTAGE * STAGE_WORDS * 4)   // 184320 B

// k-permutation within 8-groups: p(j) = (j&3)*2 + (j>>2)  (pairs (k,k+4) adjacent)
#define PERM8(j)  ((((j) & 3) << 1) | ((j) >> 2))
#define IPERM8(q) ((((q) >> 1)) | (((q) & 1) << 2))

// ---------------- scratch (device globals; no allocation allowed) ----------
__device__ float g_h0[(size_t)Ee * HIDc];   // k-permuted storage
__device__ float g_h1[(size_t)Ee * HIDc];   // k-permuted storage
__device__ float g_c [(size_t)Ee * HIDc];   // canonical
__device__ float g_a [(size_t)Ee * Hh];
__device__ float g_amax[(size_t)Nn * Hh];
__device__ float g_den [(size_t)Nn * Hh];
// tf32-pre-rounded, k-permuted operand copies
__device__ float g_Wih_t [4 * HIDc * Dd];
__device__ float g_Whh_t [(size_t)4 * HIDc * HIDc];
__device__ float g_feat_t[(size_t)Nn * Dd];
__device__ float g_attn2_t[Hh * Dd];        // permuted copy (full fp32)

// ---------------- helpers ----------------------------------------------------
__device__ __forceinline__ uint32_t f2tf(float f) {
    uint32_t r;
    asm("cvt.rna.tf32.f32 %0, %1;" : "=r"(r) : "f"(f));
    return r;
}
__device__ __forceinline__ uint32_t smem_u32(const void* p) {
    uint32_t a;
    asm("{ .reg .u64 t; cvta.to.shared.u64 t, %1; cvt.u32.u64 %0, t; }"
        : "=r"(a) : "l"(p));
    return a;
}
static __device__ __forceinline__ void cpa16(uint32_t dst, const void* src) {
    asm volatile("cp.async.cg.shared.global [%0], [%1], 16;" :: "r"(dst), "l"(src));
}
#define CP_COMMIT() asm volatile("cp.async.commit_group;")
#define CP_WAIT2()  asm volatile("cp.async.wait_group 2;")

__device__ __forceinline__ void mma8(float* d, uint32_t a0, uint32_t a1,
                                     uint32_t a2, uint32_t a3,
                                     uint32_t b0, uint32_t b1) {
    asm volatile(
        "mma.sync.aligned.m16n8k8.row.col.f32.tf32.tf32.f32 "
        "{%0,%1,%2,%3}, {%4,%5,%6,%7}, {%8,%9}, {%0,%1,%2,%3};"
        : "+f"(d[0]), "+f"(d[1]), "+f"(d[2]), "+f"(d[3])
        : "r"(a0), "r"(a1), "r"(a2), "r"(a3), "r"(b0), "r"(b1));
}

// ---------------- prep: tf32-round + k-permute weights/features --------------
__global__ void prep_kernel(const float* __restrict__ Wih,
                            const float* __restrict__ Whh,
                            const float* __restrict__ feat,
                            const float* __restrict__ attn2) {
    int i = blockIdx.x * blockDim.x + threadIdx.x;
    int d = (i & ~7) | PERM8(i & 7);
    if (i < 4 * HIDc * Dd)   g_Wih_t[d]  = __uint_as_float(f2tf(Wih[i]));
    if (i < 4 * HIDc * HIDc) g_Whh_t[d]  = __uint_as_float(f2tf(Whh[i]));
    if (i < Nn * Dd)         g_feat_t[d] = __uint_as_float(f2tf(feat[i]));
    if (i < Hh * Dd)         g_attn2_t[d] = attn2[i];
}

// ---------------- init -------------------------------------------------------
__global__ void init_kernel(float* __restrict__ out) {
    int i = blockIdx.x * blockDim.x + threadIdx.x;
    if (i < Nn * HIDc) out[i] = 0.f;
    if (i < Nn * Hh) {
        g_amax[i] = __int_as_float(0xFF800000);
        g_den[i]  = 0.f;
    }
}

// ---------------- tensor-core (mma.sync tf32) LSTM step ----------------------
// CTA: 256 edges x 32 hidden (128 gate cols), 512 threads (16 warps = 8M x 2N),
// K streamed by 32 through a 3-stage cp.async ring from k-permuted tf32 buffers.
// Permuted k makes all mma fragment loads LDS.64.
__global__ __launch_bounds__(512, 1)
void lstm_mma_kernel(const int*   __restrict__ idx,
                     const float* __restrict__ bih,
                     const float* __restrict__ bhh,
                     int t)
{
    extern __shared__ uint32_t smem[];
    __shared__ int   rows_s[BM];
    __shared__ float bias_s[128];

    const int tid   = threadIdx.x;
    const int wid   = tid >> 5;
    const int lane  = tid & 31;
    const int warpM = wid & 7;        // 0..7 (rows)
    const int warpN = wid >> 3;       // 0..1 (hidden halves)
    const int e0    = blockIdx.x * BM;
    const int nh0   = blockIdx.y * BNH;

    const float* hprev = (t & 1) ? g_h0 : g_h1;
    float*       hnext = (t & 1) ? g_h1 : g_h0;
    const bool   first = (t == 0);
    const int    NC    = first ? 2 : 18;      // K chunks: 64 feat (+512 hidden)

    if (tid < BM) {
        int e = e0 + tid; if (e >= Ee) e = Ee - 1;
        rows_s[tid] = idx[e * Ll + t];
    }
    if (tid < 128) {   // bias, c = g*32 + hh (canonical hidden order)
        int g = tid >> 5, hh = tid & 31;
        int r = g * HIDc + nh0 + hh;
        bias_s[tid] = bih[r] + bhh[r];
    }
    __syncthreads();   // rows_s ready before first cp.async fill

    // A fill: row rA (0..255), k-half (16 words = 4x16B)
    const int rA    = tid & 255;
    const int k0A   = (tid >> 8) * 16;
    // B fill: row rB (0..127 gate cols), k-quarter (8 words = 2x16B)
    const int rB    = tid & 127;
    const int k0B   = ((tid >> 7) & 3) * 8;
    const int wrow  = (rB >> 5) * HIDc + nh0 + (rB & 31);
    const uint32_t smem_base = smem_u32(smem);
    int eA = e0 + rA; if (eA >= Ee) eA = Ee - 1;

    auto fill = [&](int kc) {
        const int s = kc % NSTAGE;
        uint32_t abase = smem_base + (uint32_t)(s * STAGE_WORDS + rA * LDSW + k0A) * 4u;
        uint32_t bbase = smem_base + (uint32_t)(s * STAGE_WORDS + A_WORDS + rB * LDSW + k0B) * 4u;
        const float* ap = (kc < 2)
            ? g_feat_t + (size_t)rows_s[rA] * Dd + kc * BK + k0A
            : hprev    + (size_t)eA * HIDc + (kc - 2) * BK + k0A;
        const float* bp = (kc < 2)
            ? g_Wih_t + (size_t)wrow * Dd   + kc * BK + k0B
            : g_Whh_t + (size_t)wrow * HIDc + (kc - 2) * BK + k0B;
#pragma unroll
        for (int q = 0; q < 4; q++) cpa16(abase + q * 16, ap + q * 4);
#pragma unroll
        for (int q = 0; q < 2; q++) cpa16(bbase + q * 16, bp + q * 4);
    };

    float acc[2][2][4][4];
#pragma unroll
    for (int mb = 0; mb < 2; mb++)
#pragma unroll
        for (int nb = 0; nb < 2; nb++)
#pragma unroll
            for (int g = 0; g < 4; g++)
#pragma unroll
                for (int v = 0; v < 4; v++) acc[mb][nb][g][v] = 0.f;

    // prologue: fill 3 stages (commit empty groups to keep the count regular)
#pragma unroll
    for (int s = 0; s < NSTAGE; s++) {
        if (s < NC) fill(s);
        CP_COMMIT();
    }

    const int arow = warpM * 32 + (lane >> 2);
    const int kl2  = (lane & 3) * 2;          // permuted: (k, k+4) adjacent

    for (int kc = 0; kc < NC; kc++) {
        const int s = kc % NSTAGE;
        CP_WAIT2();                 // stage kc resident
        __syncthreads();

        const uint32_t* Ab = smem + s * STAGE_WORDS;
        const uint32_t* Bb = Ab + A_WORDS;
#pragma unroll
        for (int kk = 0; kk < 4; kk++) {
            uint2 afr0[2], afr1[2];
#pragma unroll
            for (int mb = 0; mb < 2; mb++) {
                const uint32_t* A0 = Ab + (arow + mb * 16) * LDSW + kk * 8 + kl2;
                afr0[mb] = *(const uint2*)A0;              // (a0, a2)
                afr1[mb] = *(const uint2*)(A0 + 8 * LDSW); // (a1, a3)
            }
#pragma unroll
            for (int nb = 0; nb < 2; nb++) {
                int colb = warpN * 16 + nb * 8 + (lane >> 2);
#pragma unroll
                for (int g = 0; g < 4; g++) {
                    uint2 bf = *(const uint2*)(Bb + (g * 32 + colb) * LDSW + kk * 8 + kl2);
                    mma8(acc[0][nb][g], afr0[0].x, afr1[0].x, afr0[0].y, afr1[0].y, bf.x, bf.y);
                    mma8(acc[1][nb][g], afr0[1].x, afr1[1].x, afr0[1].y, afr1[1].y, bf.x, bf.y);
                }
            }
        }
        __syncthreads();            // all warps done reading stage s
        if (kc + NSTAGE < NC) fill(kc + NSTAGE);
        CP_COMMIT();
    }

    // ---- epilogue: LSTM cell from accumulators ------------------------------
#pragma unroll
    for (int mb = 0; mb < 2; mb++) {
#pragma unroll
        for (int rh = 0; rh < 2; rh++) {
            int e = e0 + warpM * 32 + mb * 16 + (lane >> 2) + rh * 8;
            if (e >= Ee) continue;
            float* cp = g_c   + (size_t)e * HIDc + nh0;
            float* hp = hnext + (size_t)e * HIDc + nh0;
#pragma unroll
            for (int nb = 0; nb < 2; nb++) {
                int hh = warpN * 16 + nb * 8 + (lane & 3) * 2;  // canonical, even
                float2 cold = make_float2(0.f, 0.f);
                if (!first) cold = *(const float2*)(cp + hh);
                float cv[2], hv[2];
#pragma unroll
                for (int v = 0; v < 2; v++) {
                    int ci = rh * 2 + v;
                    float gi = acc[mb][nb][0][ci] + bias_s[      hh + v];
                    float gf = acc[mb][nb][1][ci] + bias_s[ 32 + hh + v];
                    float gg = acc[mb][nb][2][ci] + bias_s[ 64 + hh + v];
                    float go = acc[mb][nb][3][ci] + bias_s[ 96 + hh + v];
                    float si = 1.f / (1.f + __expf(-gi));
                    float sf = 1.f / (1.f + __expf(-gf));
                    float tg = tanhf(gg);
                    float so = 1.f / (1.f + __expf(-go));
                    float co = v ? cold.y : cold.x;
                    float cn = sf * co + si * tg;
                    cv[v] = cn;
                    hv[v] = __uint_as_float(f2tf(so * tanhf(cn)));
                }
                *(float2*)(cp + hh) = make_float2(cv[0], cv[1]);
                // h stored k-PERMUTED (it is next step's A operand)
                int b8 = hh & ~7, j = hh & 7;
                hp[b8 + PERM8(j)]     = hv[0];
                hp[b8 + PERM8(j + 1)] = hv[1];
            }
        }
    }
}

// ---------------- attention logits + segment max (warp per edge) -----------
// eft (g_h1) is k-permuted; g_attn2_t carries the same permutation -> dot OK.
__global__ void attn_logits_kernel(const float* __restrict__ feat,
                                   const int*   __restrict__ idx,
                                   const int*   __restrict__ dst,
                                   const float* __restrict__ attn1w)
{
    int warp = (blockIdx.x * blockDim.x + threadIdx.x) >> 5;
    int lane = threadIdx.x & 31;
    if (warp >= Ee) return;
    const float* hlast = g_h1;

    int h   = lane >> 2;
    int seg = lane & 3;

    const float* eft = hlast + (size_t)warp * HIDc + h * Dd;
    const float* w2  = g_attn2_t + h * Dd;
    int cidx = idx[warp * Ll + (Ll - 1)];
    const float* ctr = feat + (size_t)cidx * Dd;
    const float* w1  = attn1w + h * Dd;

    float s = 0.f;
#pragma unroll
    for (int q = 0; q < 4; q++) {
        int o = seg * 16 + q * 4;
        float4 ev = *(const float4*)(eft + o);
        float4 wv = *(const float4*)(w2 + o);
        float4 cv = *(const float4*)(ctr + o);
        float4 av = *(const float4*)(w1 + o);
        s += ev.x * wv.x + ev.y * wv.y + ev.z * wv.z + ev.w * wv.w;
        s += cv.x * av.x + cv.y * av.y + cv.z * av.z + cv.w * av.w;
    }
    s += __shfl_down_sync(0xffffffffu, s, 2);
    s += __shfl_down_sync(0xffffffffu, s, 1);

    if (seg == 0) {
        float a = (s > 0.f) ? s : 0.01f * s;
        g_a[(size_t)warp * Hh + h] = a;
        float* addr = &g_amax[(size_t)dst[warp] * Hh + h];
        if (a >= 0.f) atomicMax((int*)addr, __float_as_int(a));
        else          atomicMin((unsigned int*)addr, __float_as_uint(a));
    }
}

// ---------------- exp + denominator -----------------------------------------
__global__ void softmax_norm_kernel(const int* __restrict__ dst) {
    int i = blockIdx.x * blockDim.x + threadIdx.x;
    if (i >= Ee * Hh) return;
    int e = i >> 3, h = i & 7;
    int d = dst[e];
    float ex = __expf(g_a[i] - g_amax[(size_t)d * Hh + h]);
    g_a[i] = ex;
    atomicAdd(&g_den[(size_t)d * Hh + h], ex);
}

// ---------------- weighted segment scatter ----------------------------------
// g_h1 is k-permuted; map storage col -> canonical col for the output index.
__global__ void scatter_out_kernel(const int* __restrict__ dst,
                                   float* __restrict__ out) {
    int i = blockIdx.x * blockDim.x + threadIdx.x;
    if (i >= Ee * HIDc) return;
    int e = i >> 9, colp = i & 511, h = colp >> 6;   // head invariant under perm
    int q = colp & 7;
    int col = (colp & ~7) | IPERM8(q);
    int d = dst[e];
    float w = g_a[(size_t)e * Hh + h] / g_den[(size_t)d * Hh + h];
    atomicAdd(out + (size_t)d * HIDc + col, g_h1[i] * w);
}

// ---------------- launch ------------------------------------------------------
extern "C" void kernel_launch(void* const* d_in, const int* in_sizes, int n_in,
                              void* d_out, int out_size)
{
    const float* feat = (const float*)d_in[0];
    const int*   idx  = (const int*)d_in[2];
    const int*   dst  = (const int*)d_in[3];
    const float* Wih  = (const float*)d_in[4];
    const float* Whh  = (const float*)d_in[5];
    const float* bih  = (const float*)d_in[6];
    const float* bhh  = (const float*)d_in[7];
    const float* a1w  = (const float*)d_in[8];
    const float* a2w  = (const float*)d_in[9];
    float* out = (float*)d_out;

    cudaFuncSetAttribute(lstm_mma_kernel,
                         cudaFuncAttributeMaxDynamicSharedMemorySize, DYN_SMEM);

    prep_kernel<<<(Nn * Dd + 255) / 256, 256>>>(Wih, Whh, feat, a2w);
    init_kernel<<<(Nn * HIDc + 255) / 256, 256>>>(out);

    dim3 lgrid((Ee + BM - 1) / BM, HIDc / BNH);   // 391 x 16
    for (int t = 0; t < Ll; t++)
        lstm_mma_kernel<<<lgrid, 512, DYN_SMEM>>>(idx, bih, bhh, t);

    attn_logits_kernel<<<(Ee * 32 + 255) / 256, 256>>>(feat, idx, dst, a1w);
    softmax_norm_kernel<<<(Ee * Hh + 255) / 256, 256>>>(dst);
    scatter_out_kernel<<<(Ee * HIDc + 255) / 256, 256>>>(dst, out);
}

// round 7
// speedup vs baseline: 1.0099x; 1.0099x over previous
#include <cuda_runtime.h>
#include <math.h>
#include <stdint.h>

// Problem constants (fixed-shape problem)
#define Nn   20000
#define Ee   100000
#define Ll   4
#define Dd   64
#define Hh   8
#define HIDc 512

// mma.sync tf32 LSTM tiling (R5 structure: 128x32, 8 warps, 2 CTAs/SM)
#define BM   128        // edges per CTA
#define BNH  32         // hidden units per CTA -> 128 gate columns
#define BK   32         // K per chunk
#define LDSW 40         // smem row stride words (32+8 pad: LDS.64 conflict-free)
#define TILE_WORDS (BM * LDSW)                 // 5120 (A) ; B also 128 rows
#define STAGE_WORDS (2 * TILE_WORDS)           // A + B = 10240 words
#define DYN_SMEM    (2 * STAGE_WORDS * 4)      // 2 stages = 81920 B

// k-permutation within 8-groups: p(j) = (j&3)*2 + (j>>2)  (pairs (k,k+4) adjacent)
#define PERM8(j)  ((((j) & 3) << 1) | ((j) >> 2))
#define IPERM8(q) ((((q) >> 1)) | (((q) & 1) << 2))

// ---------------- scratch (device globals; no allocation allowed) ----------
__device__ float g_h0[(size_t)Ee * HIDc];   // k-permuted storage
__device__ float g_h1[(size_t)Ee * HIDc];   // k-permuted storage
__device__ float g_c [(size_t)Ee * HIDc];   // canonical
__device__ float g_a [(size_t)Ee * Hh];
__device__ float g_amax[(size_t)Nn * Hh];
__device__ float g_den [(size_t)Nn * Hh];
// tf32-pre-rounded, k-permuted operand copies
__device__ float g_Wih_t [4 * HIDc * Dd];
__device__ float g_Whh_t [(size_t)4 * HIDc * HIDc];
__device__ float g_feat_t[(size_t)Nn * Dd];
__device__ float g_attn2_t[Hh * Dd];        // permuted copy (full fp32)

// ---------------- helpers ----------------------------------------------------
__device__ __forceinline__ uint32_t f2tf(float f) {
    uint32_t r;
    asm("cvt.rna.tf32.f32 %0, %1;" : "=r"(r) : "f"(f));
    return r;
}
__device__ __forceinline__ uint32_t smem_u32(const void* p) {
    uint32_t a;
    asm("{ .reg .u64 t; cvta.to.shared.u64 t, %1; cvt.u32.u64 %0, t; }"
        : "=r"(a) : "l"(p));
    return a;
}
static __device__ __forceinline__ void cpa16(uint32_t dst, const void* src) {
    asm volatile("cp.async.cg.shared.global [%0], [%1], 16;" :: "r"(dst), "l"(src));
}
#define CP_COMMIT() asm volatile("cp.async.commit_group;")
#define CP_WAIT1()  asm volatile("cp.async.wait_group 1;")

__device__ __forceinline__ void mma8(float* d, uint32_t a0, uint32_t a1,
                                     uint32_t a2, uint32_t a3,
                                     uint32_t b0, uint32_t b1) {
    asm volatile(
        "mma.sync.aligned.m16n8k8.row.col.f32.tf32.tf32.f32 "
        "{%0,%1,%2,%3}, {%4,%5,%6,%7}, {%8,%9}, {%0,%1,%2,%3};"
        : "+f"(d[0]), "+f"(d[1]), "+f"(d[2]), "+f"(d[3])
        : "r"(a0), "r"(a1), "r"(a2), "r"(a3), "r"(b0), "r"(b1));
}

// ---------------- prep: tf32-round + k-permute weights/features --------------
__global__ void prep_kernel(const float* __restrict__ Wih,
                            const float* __restrict__ Whh,
                            const float* __restrict__ feat,
                            const float* __restrict__ attn2) {
    int i = blockIdx.x * blockDim.x + threadIdx.x;
    int d = (i & ~7) | PERM8(i & 7);
    if (i < 4 * HIDc * Dd)   g_Wih_t[d]  = __uint_as_float(f2tf(Wih[i]));
    if (i < 4 * HIDc * HIDc) g_Whh_t[d]  = __uint_as_float(f2tf(Whh[i]));
    if (i < Nn * Dd)         g_feat_t[d] = __uint_as_float(f2tf(feat[i]));
    if (i < Hh * Dd)         g_attn2_t[d] = attn2[i];
}

// ---------------- init -------------------------------------------------------
__global__ void init_kernel(float* __restrict__ out) {
    int i = blockIdx.x * blockDim.x + threadIdx.x;
    if (i < Nn * HIDc) out[i] = 0.f;
    if (i < Nn * Hh) {
        g_amax[i] = __int_as_float(0xFF800000);
        g_den[i]  = 0.f;
    }
}

// ---------------- tensor-core (mma.sync tf32) LSTM step ----------------------
// gates(E x 2048) = x_t @ W_ih^T + h_prev @ W_hh^T (+bias in epilogue).
// CTA: 128 edges x 32 hidden (128 gate cols), K double-buffered by 32 via
// cp.async from pre-rounded k-PERMUTED tf32 buffers: fragment loads are LDS.64.
// 2 CTAs/SM. Warp = 32 rows x 16 hidden x 4 gates.
__global__ __launch_bounds__(256, 2)
void lstm_mma_kernel(const int*   __restrict__ idx,
                     const float* __restrict__ bih,
                     const float* __restrict__ bhh,
                     int t)
{
    extern __shared__ uint32_t smem[];
    __shared__ int   rows_s[BM];
    __shared__ float bias_s[128];

    const int tid   = threadIdx.x;
    const int wid   = tid >> 5;
    const int lane  = tid & 31;
    const int warpM = wid & 3;        // 0..3 (rows)
    const int warpN = wid >> 2;       // 0..1 (hidden halves)
    const int e0    = blockIdx.x * BM;
    const int nh0   = blockIdx.y * BNH;

    const float* hprev = (t & 1) ? g_h0 : g_h1;
    float*       hnext = (t & 1) ? g_h1 : g_h0;
    const bool   first = (t == 0);
    const int    NC    = first ? 2 : 18;      // K chunks: 64 feat (+512 hidden)

    if (tid < BM) {
        int e = e0 + tid; if (e >= Ee) e = Ee - 1;
        rows_s[tid] = idx[e * Ll + t];
    }
    if (tid < 128) {   // bias, c = g*32 + hh (canonical hidden order)
        int g = tid >> 5, hh = tid & 31;
        int r = g * HIDc + nh0 + hh;
        bias_s[tid] = bih[r] + bhh[r];
    }
    __syncthreads();   // rows_s ready before first cp.async fill

    // fill-lane mapping: row r (0..127), k-half (16 words = 4x16B) for A and B
    const int r     = tid & 127;
    const int k0loc = (tid >> 7) * 16;
    const int wrow  = (r >> 5) * HIDc + nh0 + (r & 31);
    const uint32_t smem_base = smem_u32(smem);
    int eA = e0 + r; if (eA >= Ee) eA = Ee - 1;

    auto fill = [&](int kc) {
        const int s = kc & 1;
        uint32_t abase = smem_base + (uint32_t)(s * STAGE_WORDS + r * LDSW + k0loc) * 4u;
        uint32_t bbase = abase + (uint32_t)TILE_WORDS * 4u;
        const float* ap = (kc < 2)
            ? g_feat_t + (size_t)rows_s[r] * Dd + kc * BK + k0loc
            : hprev    + (size_t)eA * HIDc + (kc - 2) * BK + k0loc;
        const float* bp = (kc < 2)
            ? g_Wih_t + (size_t)wrow * Dd   + kc * BK + k0loc
            : g_Whh_t + (size_t)wrow * HIDc + (kc - 2) * BK + k0loc;
#pragma unroll
        for (int q = 0; q < 4; q++) {
            cpa16(abase + q * 16, ap + q * 4);
            cpa16(bbase + q * 16, bp + q * 4);
        }
    };

    float acc[2][2][4][4];
#pragma unroll
    for (int mb = 0; mb < 2; mb++)
#pragma unroll
        for (int nb = 0; nb < 2; nb++)
#pragma unroll
            for (int g = 0; g < 4; g++)
#pragma unroll
                for (int v = 0; v < 4; v++) acc[mb][nb][g][v] = 0.f;

    // prologue: fill stages 0 and 1
    fill(0); CP_COMMIT();
    if (NC > 1) fill(1);
    CP_COMMIT();
    CP_WAIT1();
    __syncthreads();

    const int arow = warpM * 32 + (lane >> 2);
    const int kl2  = (lane & 3) * 2;          // permuted: (k, k+4) adjacent

    for (int kc = 0; kc < NC; kc++) {
        const int buf = kc & 1;
        const uint32_t* Ab = smem + buf * STAGE_WORDS;
        const uint32_t* Bb = Ab + TILE_WORDS;
#pragma unroll
        for (int kk = 0; kk < 4; kk++) {
            uint2 afr0[2], afr1[2];
#pragma unroll
            for (int mb = 0; mb < 2; mb++) {
                const uint32_t* A0 = Ab + (arow + mb * 16) * LDSW + kk * 8 + kl2;
                afr0[mb] = *(const uint2*)A0;              // (a0, a2)
                afr1[mb] = *(const uint2*)(A0 + 8 * LDSW); // (a1, a3)
            }
#pragma unroll
            for (int nb = 0; nb < 2; nb++) {
                int colb = warpN * 16 + nb * 8 + (lane >> 2);
#pragma unroll
                for (int g = 0; g < 4; g++) {
                    uint2 bf = *(const uint2*)(Bb + (g * 32 + colb) * LDSW + kk * 8 + kl2);
                    mma8(acc[0][nb][g], afr0[0].x, afr1[0].x, afr0[0].y, afr1[0].y, bf.x, bf.y);
                    mma8(acc[1][nb][g], afr0[1].x, afr1[1].x, afr0[1].y, afr1[1].y, bf.x, bf.y);
                }
            }
        }
        if (kc + 1 < NC) {
            __syncthreads();               // all warps done reading buf
            if (kc + 2 < NC) fill(kc + 2); // refill this buf
            CP_COMMIT();
            CP_WAIT1();                    // stage kc+1 resident
            __syncthreads();
        }
    }

    // ---- epilogue: LSTM cell from accumulators ------------------------------
#pragma unroll
    for (int mb = 0; mb < 2; mb++) {
#pragma unroll
        for (int rh = 0; rh < 2; rh++) {
            int e = e0 + warpM * 32 + mb * 16 + (lane >> 2) + rh * 8;
            if (e >= Ee) continue;
            float* cp = g_c   + (size_t)e * HIDc + nh0;
            float* hp = hnext + (size_t)e * HIDc + nh0;
#pragma unroll
            for (int nb = 0; nb < 2; nb++) {
                int hh = warpN * 16 + nb * 8 + (lane & 3) * 2;  // canonical, even
                float2 cold = make_float2(0.f, 0.f);
                if (!first) cold = *(const float2*)(cp + hh);
                float cv[2], hv[2];
#pragma unroll
                for (int v = 0; v < 2; v++) {
                    int ci = rh * 2 + v;
                    float gi = acc[mb][nb][0][ci] + bias_s[      hh + v];
                    float gf = acc[mb][nb][1][ci] + bias_s[ 32 + hh + v];
                    float gg = acc[mb][nb][2][ci] + bias_s[ 64 + hh + v];
                    float go = acc[mb][nb][3][ci] + bias_s[ 96 + hh + v];
                    float si = 1.f / (1.f + __expf(-gi));
                    float sf = 1.f / (1.f + __expf(-gf));
                    float tg = tanhf(gg);
                    float so = 1.f / (1.f + __expf(-go));
                    float co = v ? cold.y : cold.x;
                    float cn = sf * co + si * tg;
                    cv[v] = cn;
                    hv[v] = __uint_as_float(f2tf(so * tanhf(cn)));
                }
                *(float2*)(cp + hh) = make_float2(cv[0], cv[1]);
                // h stored k-PERMUTED (it is next step's A operand)
                int b8 = hh & ~7, j = hh & 7;
                hp[b8 + PERM8(j)]     = hv[0];
                hp[b8 + PERM8(j + 1)] = hv[1];
            }
        }
    }
}

// ---------------- attention logits + segment max (warp per edge) -----------
// eft (g_h1) is k-permuted; g_attn2_t carries the same permutation -> dot OK.
__global__ void attn_logits_kernel(const float* __restrict__ feat,
                                   const int*   __restrict__ idx,
                                   const int*   __restrict__ dst,
                                   const float* __restrict__ attn1w)
{
    int warp = (blockIdx.x * blockDim.x + threadIdx.x) >> 5;
    int lane = threadIdx.x & 31;
    if (warp >= Ee) return;
    const float* hlast = g_h1;

    int h   = lane >> 2;
    int seg = lane & 3;

    const float* eft = hlast + (size_t)warp * HIDc + h * Dd;
    const float* w2  = g_attn2_t + h * Dd;
    int cidx = idx[warp * Ll + (Ll - 1)];
    const float* ctr = feat + (size_t)cidx * Dd;
    const float* w1  = attn1w + h * Dd;

    float s = 0.f;
#pragma unroll
    for (int q = 0; q < 4; q++) {
        int o = seg * 16 + q * 4;
        float4 ev = *(const float4*)(eft + o);
        float4 wv = *(const float4*)(w2 + o);
        float4 cv = *(const float4*)(ctr + o);
        float4 av = *(const float4*)(w1 + o);
        s += ev.x * wv.x + ev.y * wv.y + ev.z * wv.z + ev.w * wv.w;
        s += cv.x * av.x + cv.y * av.y + cv.z * av.z + cv.w * av.w;
    }
    s += __shfl_down_sync(0xffffffffu, s, 2);
    s += __shfl_down_sync(0xffffffffu, s, 1);

    if (seg == 0) {
        float a = (s > 0.f) ? s : 0.01f * s;
        g_a[(size_t)warp * Hh + h] = a;
        float* addr = &g_amax[(size_t)dst[warp] * Hh + h];
        if (a >= 0.f) atomicMax((int*)addr, __float_as_int(a));
        else          atomicMin((unsigned int*)addr, __float_as_uint(a));
    }
}

// ---------------- exp + denominator -----------------------------------------
__global__ void softmax_norm_kernel(const int* __restrict__ dst) {
    int i = blockIdx.x * blockDim.x + threadIdx.x;
    if (i >= Ee * Hh) return;
    int e = i >> 3, h = i & 7;
    int d = dst[e];
    float ex = __expf(g_a[i] - g_amax[(size_t)d * Hh + h]);
    g_a[i] = ex;
    atomicAdd(&g_den[(size_t)d * Hh + h], ex);
}

// ---------------- weighted segment scatter ----------------------------------
// g_h1 is k-permuted; map storage col -> canonical col for the output index.
__global__ void scatter_out_kernel(const int* __restrict__ dst,
                                   float* __restrict__ out) {
    int i = blockIdx.x * blockDim.x + threadIdx.x;
    if (i >= Ee * HIDc) return;
    int e = i >> 9, colp = i & 511, h = colp >> 6;   // head invariant under perm
    int q = colp & 7;
    int col = (colp & ~7) | IPERM8(q);
    int d = dst[e];
    float w = g_a[(size_t)e * Hh + h] / g_den[(size_t)d * Hh + h];
    atomicAdd(out + (size_t)d * HIDc + col, g_h1[i] * w);
}

// ---------------- launch ------------------------------------------------------
extern "C" void kernel_launch(void* const* d_in, const int* in_sizes, int n_in,
                              void* d_out, int out_size)
{
    const float* feat = (const float*)d_in[0];
    const int*   idx  = (const int*)d_in[2];
    const int*   dst  = (const int*)d_in[3];
    const float* Wih  = (const float*)d_in[4];
    const float* Whh  = (const float*)d_in[5];
    const float* bih  = (const float*)d_in[6];
    const float* bhh  = (const float*)d_in[7];
    const float* a1w  = (const float*)d_in[8];
    const float* a2w  = (const float*)d_in[9];
    float* out = (float*)d_out;

    cudaFuncSetAttribute(lstm_mma_kernel,
                         cudaFuncAttributeMaxDynamicSharedMemorySize, DYN_SMEM);

    prep_kernel<<<(Nn * Dd + 255) / 256, 256>>>(Wih, Whh, feat, a2w);
    init_kernel<<<(Nn * HIDc + 255) / 256, 256>>>(out);

    dim3 lgrid((Ee + BM - 1) / BM, HIDc / BNH);   // 782 x 16
    for (int t = 0; t < Ll; t++)
        lstm_mma_kernel<<<lgrid, 256, DYN_SMEM>>>(idx, bih, bhh, t);

    attn_logits_kernel<<<(Ee * 32 + 255) / 256, 256>>>(feat, idx, dst, a1w);
    softmax_norm_kernel<<<(Ee * Hh + 255) / 256, 256>>>(dst);
    scatter_out_kernel<<<(Ee * HIDc + 255) / 256, 256>>>(dst, out);
}

// round 8
// speedup vs baseline: 1.1145x; 1.1036x over previous
#include <cuda_runtime.h>
#include <math.h>
#include <stdint.h>

// Problem constants (fixed-shape problem)
#define Nn   20000
#define Ee   100000
#define Ll   4
#define Dd   64
#define Hh   8
#define HIDc 512

// mma.sync tf32 LSTM tiling (R5 structure: 128x32, 8 warps, 2 CTAs/SM)
#define BM   128        // edges per CTA
#define BNH  32         // hidden units per CTA -> 128 gate columns
#define BK   32         // K per chunk
#define LDSW 36         // smem row stride in words (32 + 4 pad: conflict-free frags)
#define TILE_WORDS (BM * LDSW)                 // 4608
#define STAGE_WORDS (2 * TILE_WORDS)           // A + B = 9216 words
#define NSTAGE 3
#define DYN_SMEM (NSTAGE * STAGE_WORDS * 4)    // 110592 B -> 2 CTAs/SM

// ---------------- scratch (device globals; no allocation allowed) ----------
__device__ float g_h0[(size_t)Ee * HIDc];
__device__ float g_h1[(size_t)Ee * HIDc];
__device__ float g_c [(size_t)Ee * HIDc];
__device__ float g_a [(size_t)Ee * Hh];
__device__ float g_amax[(size_t)Nn * Hh];
__device__ float g_den [(size_t)Nn * Hh];
// tf32-pre-rounded operand copies (fp32 bit patterns, low mantissa zeroed)
__device__ float g_Wih_t [4 * HIDc * Dd];          // 2048 x 64
__device__ float g_Whh_t [(size_t)4 * HIDc * HIDc];// 2048 x 512
__device__ float g_feat_t[(size_t)Nn * Dd];        // 20000 x 64

// ---------------- helpers ----------------------------------------------------
__device__ __forceinline__ uint32_t f2tf(float f) {
    uint32_t r;
    asm("cvt.rna.tf32.f32 %0, %1;" : "=r"(r) : "f"(f));
    return r;
}
__device__ __forceinline__ uint32_t smem_u32(const void* p) {
    uint32_t a;
    asm("{ .reg .u64 t; cvta.to.shared.u64 t, %1; cvt.u32.u64 %0, t; }"
        : "=r"(a) : "l"(p));
    return a;
}
static __device__ __forceinline__ void cpa16(uint32_t dst, const void* src) {
    asm volatile("cp.async.cg.shared.global [%0], [%1], 16;" :: "r"(dst), "l"(src));
}
#define CP_COMMIT() asm volatile("cp.async.commit_group;")
#define CP_WAIT1()  asm volatile("cp.async.wait_group 1;")

__device__ __forceinline__ void mma8(float* d, const uint32_t* a,
                                     uint32_t b0, uint32_t b1) {
    asm volatile(
        "mma.sync.aligned.m16n8k8.row.col.f32.tf32.tf32.f32 "
        "{%0,%1,%2,%3}, {%4,%5,%6,%7}, {%8,%9}, {%0,%1,%2,%3};"
        : "+f"(d[0]), "+f"(d[1]), "+f"(d[2]), "+f"(d[3])
        : "r"(a[0]), "r"(a[1]), "r"(a[2]), "r"(a[3]), "r"(b0), "r"(b1));
}

// ---------------- prep: tf32-round weights + features once -------------------
__global__ void prep_kernel(const float* __restrict__ Wih,
                            const float* __restrict__ Whh,
                            const float* __restrict__ feat) {
    int i = blockIdx.x * blockDim.x + threadIdx.x;
    if (i < 4 * HIDc * Dd)   g_Wih_t[i]  = __uint_as_float(f2tf(Wih[i]));
    if (i < 4 * HIDc * HIDc) g_Whh_t[i]  = __uint_as_float(f2tf(Whh[i]));
    if (i < Nn * Dd)         g_feat_t[i] = __uint_as_float(f2tf(feat[i]));
}

// ---------------- init -------------------------------------------------------
__global__ void init_kernel(float* __restrict__ out) {
    int i = blockIdx.x * blockDim.x + threadIdx.x;
    if (i < Nn * HIDc) out[i] = 0.f;
    if (i < Nn * Hh) {
        g_amax[i] = __int_as_float(0xFF800000);
        g_den[i]  = 0.f;
    }
}

// ---------------- tensor-core (mma.sync tf32) LSTM step ----------------------
// gates(E x 2048) = x_t @ W_ih^T + h_prev @ W_hh^T (+bias in epilogue).
// CTA: 128 edges x 32 hidden (128 gate cols). K streamed by 32 through a
// 3-stage cp.async ring with ONE __syncthreads per chunk: fill at iter kc
// targets slot (kc+2)%3 == (kc-1)%3, whose consumption the top-of-loop barrier
// already ordered. 2 CTAs/SM. Warp = 32 rows x 16 hidden x 4 gates.
__global__ __launch_bounds__(256, 2)
void lstm_mma_kernel(const int*   __restrict__ idx,
                     const float* __restrict__ bih,
                     const float* __restrict__ bhh,
                     int t)
{
    extern __shared__ uint32_t smem[];
    __shared__ int   rows_s[BM];
    __shared__ float bias_s[128];

    const int tid   = threadIdx.x;
    const int wid   = tid >> 5;
    const int lane  = tid & 31;
    const int warpM = wid & 3;        // 0..3 (rows)
    const int warpN = wid >> 2;       // 0..1 (hidden halves)
    const int e0    = blockIdx.x * BM;
    const int nh0   = blockIdx.y * BNH;

    const float* hprev = (t & 1) ? g_h0 : g_h1;
    float*       hnext = (t & 1) ? g_h1 : g_h0;
    const bool   first = (t == 0);
    const int    NC    = first ? 2 : 18;      // K chunks: 64 feat (+512 hidden)

    if (tid < BM) {
        int e = e0 + tid; if (e >= Ee) e = Ee - 1;
        rows_s[tid] = idx[e * Ll + t];
    }
    if (tid < 128) {   // bias, c = g*32 + hh
        int g = tid >> 5, hh = tid & 31;
        int r = g * HIDc + nh0 + hh;
        bias_s[tid] = bih[r] + bhh[r];
    }
    __syncthreads();   // rows_s ready before first cp.async fill

    // fill-lane mapping: row r, k-half (16 floats = 4x16B each for A and B)
    const int r     = tid & 127;
    const int k0loc = (tid >> 7) * 16;
    const int wrow  = (r >> 5) * HIDc + nh0 + (r & 31);
    const uint32_t smem_base = smem_u32(smem);
    int eA = e0 + r; if (eA >= Ee) eA = Ee - 1;

    auto fill = [&](int kc) {
        const int s = kc % NSTAGE;
        uint32_t abase = smem_base + (uint32_t)(s * STAGE_WORDS + r * LDSW + k0loc) * 4u;
        uint32_t bbase = abase + (uint32_t)TILE_WORDS * 4u;
        const float* ap = (kc < 2)
            ? g_feat_t + (size_t)rows_s[r] * Dd + kc * BK + k0loc
            : hprev    + (size_t)eA * HIDc + (kc - 2) * BK + k0loc;
        const float* bp = (kc < 2)
            ? g_Wih_t + (size_t)wrow * Dd   + kc * BK + k0loc
            : g_Whh_t + (size_t)wrow * HIDc + (kc - 2) * BK + k0loc;
#pragma unroll
        for (int q = 0; q < 4; q++) {
            cpa16(abase + q * 16, ap + q * 4);
            cpa16(bbase + q * 16, bp + q * 4);
        }
    };

    float acc[2][2][4][4];
#pragma unroll
    for (int mb = 0; mb < 2; mb++)
#pragma unroll
        for (int nb = 0; nb < 2; nb++)
#pragma unroll
            for (int g = 0; g < 4; g++)
#pragma unroll
                for (int v = 0; v < 4; v++) acc[mb][nb][g][v] = 0.f;

    // prologue: fill stages 0 and 1 (NC >= 2 always)
    fill(0); CP_COMMIT();
    fill(1); CP_COMMIT();

    const int arow = warpM * 32 + (lane >> 2);
    const int kl   = lane & 3;

    for (int kc = 0; kc < NC; kc++) {
        CP_WAIT1();                 // stage kc resident (<=1 group pending)
        __syncthreads();            // publish stage kc; orders prior compute
        if (kc + 2 < NC) fill(kc + 2);   // slot (kc-1)%3: consumed last iter
        CP_COMMIT();

        const int s = kc % NSTAGE;
        const uint32_t* Ab = smem + s * STAGE_WORDS;
        const uint32_t* Bb = Ab + TILE_WORDS;
#pragma unroll
        for (int kk = 0; kk < 4; kk++) {
            uint32_t afr[2][4];
#pragma unroll
            for (int mb = 0; mb < 2; mb++) {
                const uint32_t* A0 = Ab + (arow + mb * 16) * LDSW + kk * 8 + kl;
                afr[mb][0] = A0[0];
                afr[mb][1] = A0[8 * LDSW];
                afr[mb][2] = A0[4];
                afr[mb][3] = A0[8 * LDSW + 4];
            }
#pragma unroll
            for (int nb = 0; nb < 2; nb++) {
                int colb = warpN * 16 + nb * 8 + (lane >> 2);
#pragma unroll
                for (int g = 0; g < 4; g++) {
                    const uint32_t* B0 = Bb + (g * 32 + colb) * LDSW + kk * 8 + kl;
                    uint32_t b0 = B0[0], b1 = B0[4];
                    mma8(acc[0][nb][g], afr[0], b0, b1);
                    mma8(acc[1][nb][g], afr[1], b0, b1);
                }
            }
        }
    }

    // ---- epilogue: LSTM cell from accumulators ------------------------------
#pragma unroll
    for (int mb = 0; mb < 2; mb++) {
#pragma unroll
        for (int rh = 0; rh < 2; rh++) {
            int e = e0 + warpM * 32 + mb * 16 + (lane >> 2) + rh * 8;
            if (e >= Ee) continue;
            float* cp = g_c   + (size_t)e * HIDc + nh0;
            float* hp = hnext + (size_t)e * HIDc + nh0;
#pragma unroll
            for (int nb = 0; nb < 2; nb++) {
                int hh = warpN * 16 + nb * 8 + (lane & 3) * 2;
                float2 cold = make_float2(0.f, 0.f);
                if (!first) cold = *(const float2*)(cp + hh);
                float cv[2], hv[2];
#pragma unroll
                for (int v = 0; v < 2; v++) {
                    int ci = rh * 2 + v;
                    float gi = acc[mb][nb][0][ci] + bias_s[      hh + v];
                    float gf = acc[mb][nb][1][ci] + bias_s[ 32 + hh + v];
                    float gg = acc[mb][nb][2][ci] + bias_s[ 64 + hh + v];
                    float go = acc[mb][nb][3][ci] + bias_s[ 96 + hh + v];
                    float si = 1.f / (1.f + __expf(-gi));
                    float sf = 1.f / (1.f + __expf(-gf));
                    float tg = tanhf(gg);
                    float so = 1.f / (1.f + __expf(-go));
                    float co = v ? cold.y : cold.x;
                    float cn = sf * co + si * tg;
                    cv[v] = cn;
                    // h stored pre-rounded to tf32 so next step cp.asyncs it raw
                    hv[v] = __uint_as_float(f2tf(so * tanhf(cn)));
                }
                *(float2*)(cp + hh) = make_float2(cv[0], cv[1]);
                *(float2*)(hp + hh) = make_float2(hv[0], hv[1]);
            }
        }
    }
}

// ---------------- attention logits + segment max (warp per edge) -----------
__global__ void attn_logits_kernel(const float* __restrict__ feat,
                                   const int*   __restrict__ idx,
                                   const int*   __restrict__ dst,
                                   const float* __restrict__ attn1w,
                                   const float* __restrict__ attn2)
{
    int warp = (blockIdx.x * blockDim.x + threadIdx.x) >> 5;
    int lane = threadIdx.x & 31;
    if (warp >= Ee) return;
    const float* hlast = g_h1;

    int h   = lane >> 2;
    int seg = lane & 3;

    const float* eft = hlast + (size_t)warp * HIDc + h * Dd;
    const float* w2  = attn2  + h * Dd;
    int cidx = idx[warp * Ll + (Ll - 1)];
    const float* ctr = feat + (size_t)cidx * Dd;
    const float* w1  = attn1w + h * Dd;

    float s = 0.f;
#pragma unroll
    for (int q = 0; q < 4; q++) {
        int o = seg * 16 + q * 4;
        float4 ev = *(const float4*)(eft + o);
        float4 wv = *(const float4*)(w2 + o);
        float4 cv = *(const float4*)(ctr + o);
        float4 av = *(const float4*)(w1 + o);
        s += ev.x * wv.x + ev.y * wv.y + ev.z * wv.z + ev.w * wv.w;
        s += cv.x * av.x + cv.y * av.y + cv.z * av.z + cv.w * av.w;
    }
    s += __shfl_down_sync(0xffffffffu, s, 2);
    s += __shfl_down_sync(0xffffffffu, s, 1);

    if (seg == 0) {
        float a = (s > 0.f) ? s : 0.01f * s;
        g_a[(size_t)warp * Hh + h] = a;
        float* addr = &g_amax[(size_t)dst[warp] * Hh + h];
        if (a >= 0.f) atomicMax((int*)addr, __float_as_int(a));
        else          atomicMin((unsigned int*)addr, __float_as_uint(a));
    }
}

// ---------------- exp + denominator -----------------------------------------
__global__ void softmax_norm_kernel(const int* __restrict__ dst) {
    int i = blockIdx.x * blockDim.x + threadIdx.x;
    if (i >= Ee * Hh) return;
    int e = i >> 3, h = i & 7;
    int d = dst[e];
    float ex = __expf(g_a[i] - g_amax[(size_t)d * Hh + h]);
    g_a[i] = ex;
    atomicAdd(&g_den[(size_t)d * Hh + h], ex);
}

// ---------------- weighted segment scatter ----------------------------------
__global__ void scatter_out_kernel(const int* __restrict__ dst,
                                   float* __restrict__ out) {
    int i = blockIdx.x * blockDim.x + threadIdx.x;
    if (i >= Ee * HIDc) return;
    int e = i >> 9, col = i & 511, h = col >> 6;
    int d = dst[e];
    float w = g_a[(size_t)e * Hh + h] / g_den[(size_t)d * Hh + h];
    atomicAdd(out + (size_t)d * HIDc + col, g_h1[i] * w);
}

// ---------------- launch ------------------------------------------------------
extern "C" void kernel_launch(void* const* d_in, const int* in_sizes, int n_in,
                              void* d_out, int out_size)
{
    const float* feat = (const float*)d_in[0];
    const int*   idx  = (const int*)d_in[2];
    const int*   dst  = (const int*)d_in[3];
    const float* Wih  = (const float*)d_in[4];
    const float* Whh  = (const float*)d_in[5];
    const float* bih  = (const float*)d_in[6];
    const float* bhh  = (const float*)d_in[7];
    const float* a1w  = (const float*)d_in[8];
    const float* a2w  = (const float*)d_in[9];
    float* out = (float*)d_out;

    cudaFuncSetAttribute(lstm_mma_kernel,
                         cudaFuncAttributeMaxDynamicSharedMemorySize, DYN_SMEM);

    prep_kernel<<<(Nn * Dd + 255) / 256, 256>>>(Wih, Whh, feat);
    init_kernel<<<(Nn * HIDc + 255) / 256, 256>>>(out);

    dim3 lgrid((Ee + BM - 1) / BM, HIDc / BNH);   // 782 x 16
    for (int t = 0; t < Ll; t++)
        lstm_mma_kernel<<<lgrid, 256, DYN_SMEM>>>(idx, bih, bhh, t);

    attn_logits_kernel<<<(Ee * 32 + 255) / 256, 256>>>(feat, idx, dst, a1w, a2w);
    softmax_norm_kernel<<<(Ee * Hh + 255) / 256, 256>>>(dst);
    scatter_out_kernel<<<(Ee * HIDc + 255) / 256, 256>>>(dst, out);
}

// round 10
// speedup vs baseline: 1.9810x; 1.7776x over previous
#include <cuda_runtime.h>
#include <cuda_fp16.h>
#include <math.h>
#include <stdint.h>

// Problem constants (fixed-shape problem)
#define Nn   20000
#define Ee   100000
#define Ll   4
#define Dd   64
#define Hh   8
#define HIDc 512

// mma.sync fp16 LSTM tiling (R5/R8 structure: 128x32, 8 warps, 2 CTAs/SM)
#define BM   128        // edges per CTA
#define BNH  32         // hidden units per CTA -> 128 gate columns
#define BK   32         // K per chunk (32 fp16 = 16 words)
#define LDSW 20         // smem row stride in WORDS (16 + 4 pad: conflict-free)
#define TILE_WORDS (BM * LDSW)                 // 2560
#define STAGE_WORDS (2 * TILE_WORDS)           // A + B = 5120 words
#define NSTAGE 3
#define DYN_SMEM (NSTAGE * STAGE_WORDS * 4)    // 61440 B -> 2 CTAs/SM easily

// ---------------- scratch (device globals; no allocation allowed) ----------
__device__ float  g_h1[(size_t)Ee * HIDc];     // final-step h (fp32, attn/scatter)
__device__ float  g_c [(size_t)Ee * HIDc];     // cell state (fp32)
__device__ __half g_h16a[(size_t)Ee * HIDc];   // h ping (fp16, MMA operand)
__device__ __half g_h16b[(size_t)Ee * HIDc];   // h pong
__device__ float  g_a [(size_t)Ee * Hh];
__device__ float  g_amax[(size_t)Nn * Hh];
__device__ float  g_den [(size_t)Nn * Hh];
// fp16 operand copies
__device__ __half g_Wih_h [4 * HIDc * Dd];          // 2048 x 64
__device__ __half g_Whh_h [(size_t)4 * HIDc * HIDc];// 2048 x 512
__device__ __half g_feat_h[(size_t)Nn * Dd];        // 20000 x 64

// ---------------- helpers ----------------------------------------------------
__device__ __forceinline__ uint32_t smem_u32(const void* p) {
    uint32_t a;
    asm("{ .reg .u64 t; cvta.to.shared.u64 t, %1; cvt.u32.u64 %0, t; }"
        : "=r"(a) : "l"(p));
    return a;
}
static __device__ __forceinline__ void cpa16(uint32_t dst, const void* src) {
    asm volatile("cp.async.cg.shared.global [%0], [%1], 16;" :: "r"(dst), "l"(src));
}
#define CP_COMMIT() asm volatile("cp.async.commit_group;")
#define CP_WAIT1()  asm volatile("cp.async.wait_group 1;")

// m16n8k16 fp16 inputs, fp32 accumulate. Same thread->C map as m16n8k8.
__device__ __forceinline__ void mma16(float* d, const uint32_t* a,
                                      uint32_t b0, uint32_t b1) {
    asm volatile(
        "mma.sync.aligned.m16n8k16.row.col.f32.f16.f16.f32 "
        "{%0,%1,%2,%3}, {%4,%5,%6,%7}, {%8,%9}, {%0,%1,%2,%3};"
        : "+f"(d[0]), "+f"(d[1]), "+f"(d[2]), "+f"(d[3])
        : "r"(a[0]), "r"(a[1]), "r"(a[2]), "r"(a[3]), "r"(b0), "r"(b1));
}

// ---------------- prep: fp16-round weights + features once -------------------
__global__ void prep_kernel(const float* __restrict__ Wih,
                            const float* __restrict__ Whh,
                            const float* __restrict__ feat) {
    int i = blockIdx.x * blockDim.x + threadIdx.x;
    if (i < 4 * HIDc * Dd)   g_Wih_h[i]  = __float2half_rn(Wih[i]);
    if (i < 4 * HIDc * HIDc) g_Whh_h[i]  = __float2half_rn(Whh[i]);
    if (i < Nn * Dd)         g_feat_h[i] = __float2half_rn(feat[i]);
}

// ---------------- init -------------------------------------------------------
__global__ void init_kernel(float* __restrict__ out) {
    int i = blockIdx.x * blockDim.x + threadIdx.x;
    if (i < Nn * HIDc) out[i] = 0.f;
    if (i < Nn * Hh) {
        g_amax[i] = __int_as_float(0xFF800000);
        g_den[i]  = 0.f;
    }
}

// ---------------- tensor-core (mma.sync fp16) LSTM step ----------------------
// gates(E x 2048) = x_t @ W_ih^T + h_prev @ W_hh^T (+bias in epilogue).
// CTA: 128 edges x 32 hidden (128 gate cols). K streamed by 32 through a
// 3-stage cp.async ring, one __syncthreads per chunk. fp16 operands:
// 2 MMAs (k16) per chunk per (mb,nb,g); all fragment loads scalar LDS.32
// (each word = 2 packed fp16). 2 CTAs/SM. Warp = 32 rows x 16 hidden x 4 gates.
__global__ __launch_bounds__(256, 2)
void lstm_mma_kernel(const int*   __restrict__ idx,
                     const float* __restrict__ bih,
                     const float* __restrict__ bhh,
                     int t)
{
    extern __shared__ uint32_t smem[];
    __shared__ int   rows_s[BM];
    __shared__ float bias_s[128];

    const int tid   = threadIdx.x;
    const int wid   = tid >> 5;
    const int lane  = tid & 31;
    const int warpM = wid & 3;        // 0..3 (rows)
    const int warpN = wid >> 2;       // 0..1 (hidden halves)
    const int e0    = blockIdx.x * BM;
    const int nh0   = blockIdx.y * BNH;

    const __half* hprev16 = (t & 1) ? g_h16a : g_h16b;
    __half*       hnext16 = (t & 1) ? g_h16b : g_h16a;
    const bool first = (t == 0);
    const bool last  = (t == Ll - 1);
    const int  NC    = first ? 2 : 18;        // K chunks: 64 feat (+512 hidden)

    if (tid < BM) {
        int e = e0 + tid; if (e >= Ee) e = Ee - 1;
        rows_s[tid] = idx[e * Ll + t];
    }
    if (tid < 128) {   // bias, c = g*32 + hh
        int g = tid >> 5, hh = tid & 31;
        int r = g * HIDc + nh0 + hh;
        bias_s[tid] = bih[r] + bhh[r];
    }
    __syncthreads();   // rows_s ready before first cp.async fill

    // fill-lane mapping: row r, k-half (16 fp16 = 32B = 2x16B each for A and B)
    const int r     = tid & 127;
    const int kh    = tid >> 7;               // 0/1
    const int k0e   = kh * 16;                // fp16-element offset
    const int k0w   = kh * 8;                 // word offset
    const int wrow  = (r >> 5) * HIDc + nh0 + (r & 31);
    const uint32_t smem_base = smem_u32(smem);
    int eA = e0 + r; if (eA >= Ee) eA = Ee - 1;

    auto fill = [&](int kc) {
        const int s = kc % NSTAGE;
        uint32_t abase = smem_base + (uint32_t)(s * STAGE_WORDS + r * LDSW + k0w) * 4u;
        uint32_t bbase = abase + (uint32_t)TILE_WORDS * 4u;
        const __half* ap = (kc < 2)
            ? g_feat_h + (size_t)rows_s[r] * Dd + kc * BK + k0e
            : hprev16  + (size_t)eA * HIDc + (kc - 2) * BK + k0e;
        const __half* bp = (kc < 2)
            ? g_Wih_h + (size_t)wrow * Dd   + kc * BK + k0e
            : g_Whh_h + (size_t)wrow * HIDc + (kc - 2) * BK + k0e;
        cpa16(abase,      ap);
        cpa16(abase + 16, ap + 8);
        cpa16(bbase,      bp);
        cpa16(bbase + 16, bp + 8);
    };

    float acc[2][2][4][4];
#pragma unroll
    for (int mb = 0; mb < 2; mb++)
#pragma unroll
        for (int nb = 0; nb < 2; nb++)
#pragma unroll
            for (int g = 0; g < 4; g++)
#pragma unroll
                for (int v = 0; v < 4; v++) acc[mb][nb][g][v] = 0.f;

    // prologue: fill stages 0 and 1 (NC >= 2 always)
    fill(0); CP_COMMIT();
    fill(1); CP_COMMIT();

    const int arow = warpM * 32 + (lane >> 2);
    const int kl   = lane & 3;

    for (int kc = 0; kc < NC; kc++) {
        CP_WAIT1();                 // stage kc resident (<=1 group pending)
        __syncthreads();            // publish stage kc; orders prior compute
        if (kc + 2 < NC) fill(kc + 2);   // slot (kc-1)%3: consumed last iter
        CP_COMMIT();

        const int s = kc % NSTAGE;
        const uint32_t* Ab = smem + s * STAGE_WORDS;
        const uint32_t* Bb = Ab + TILE_WORDS;
#pragma unroll
        for (int kk = 0; kk < 2; kk++) {      // 2 x k16 per 32-chunk
            uint32_t afr[2][4];
#pragma unroll
            for (int mb = 0; mb < 2; mb++) {
                const uint32_t* A0 = Ab + (arow + mb * 16) * LDSW + kk * 8 + kl;
                afr[mb][0] = A0[0];            // row r,   k = 2*kl, 2*kl+1
                afr[mb][1] = A0[8 * LDSW];     // row r+8, same k
                afr[mb][2] = A0[4];            // row r,   k + 8
                afr[mb][3] = A0[8 * LDSW + 4]; // row r+8, k + 8
            }
#pragma unroll
            for (int nb = 0; nb < 2; nb++) {
                int colb = warpN * 16 + nb * 8 + (lane >> 2);
#pragma unroll
                for (int g = 0; g < 4; g++) {
                    const uint32_t* B0 = Bb + (g * 32 + colb) * LDSW + kk * 8 + kl;
                    uint32_t b0 = B0[0], b1 = B0[4];
                    mma16(acc[0][nb][g], afr[0], b0, b1);
                    mma16(acc[1][nb][g], afr[1], b0, b1);
                }
            }
        }
    }

    // ---- epilogue: LSTM cell from accumulators ------------------------------
#pragma unroll
    for (int mb = 0; mb < 2; mb++) {
#pragma unroll
        for (int rh = 0; rh < 2; rh++) {
            int e = e0 + warpM * 32 + mb * 16 + (lane >> 2) + rh * 8;
            if (e >= Ee) continue;
            float*  cp   = g_c     + (size_t)e * HIDc + nh0;
            __half* hp16 = hnext16 + (size_t)e * HIDc + nh0;
            float*  hp32 = g_h1    + (size_t)e * HIDc + nh0;
#pragma unroll
            for (int nb = 0; nb < 2; nb++) {
                int hh = warpN * 16 + nb * 8 + (lane & 3) * 2;
                float2 cold = make_float2(0.f, 0.f);
                if (!first) cold = *(const float2*)(cp + hh);
                float cv[2], hv[2];
#pragma unroll
                for (int v = 0; v < 2; v++) {
                    int ci = rh * 2 + v;
                    float gi = acc[mb][nb][0][ci] + bias_s[      hh + v];
                    float gf = acc[mb][nb][1][ci] + bias_s[ 32 + hh + v];
                    float gg = acc[mb][nb][2][ci] + bias_s[ 64 + hh + v];
                    float go = acc[mb][nb][3][ci] + bias_s[ 96 + hh + v];
                    float si = 1.f / (1.f + __expf(-gi));
                    float sf = 1.f / (1.f + __expf(-gf));
                    float tg = tanhf(gg);
                    float so = 1.f / (1.f + __expf(-go));
                    float co = v ? cold.y : cold.x;
                    float cn = sf * co + si * tg;
                    cv[v] = cn;
                    hv[v] = so * tanhf(cn);
                }
                *(float2*)(cp + hh) = make_float2(cv[0], cv[1]);
                // fp16 h for next step's MMA A operand (low half = element hh)
                *(__half2*)(hp16 + hh) = __floats2half2_rn(hv[0], hv[1]);
                // fp32 h only needed after the last step (attention/scatter)
                if (last) *(float2*)(hp32 + hh) = make_float2(hv[0], hv[1]);
            }
        }
    }
}

// ---------------- attention logits + segment max (warp per edge) -----------
__global__ void attn_logits_kernel(const float* __restrict__ feat,
                                   const int*   __restrict__ idx,
                                   const int*   __restrict__ dst,
                                   const float* __restrict__ attn1w,
                                   const float* __restrict__ attn2)
{
    int warp = (blockIdx.x * blockDim.x + threadIdx.x) >> 5;
    int lane = threadIdx.x & 31;
    if (warp >= Ee) return;
    const float* hlast = g_h1;

    int h   = lane >> 2;
    int seg = lane & 3;

    const float* eft = hlast + (size_t)warp * HIDc + h * Dd;
    const float* w2  = attn2  + h * Dd;
    int cidx = idx[warp * Ll + (Ll - 1)];
    const float* ctr = feat + (size_t)cidx * Dd;
    const float* w1  = attn1w + h * Dd;

    float s = 0.f;
#pragma unroll
    for (int q = 0; q < 4; q++) {
        int o = seg * 16 + q * 4;
        float4 ev = *(const float4*)(eft + o);
        float4 wv = *(const float4*)(w2 + o);
        float4 cv = *(const float4*)(ctr + o);
        float4 av = *(const float4*)(w1 + o);
        s += ev.x * wv.x + ev.y * wv.y + ev.z * wv.z + ev.w * wv.w;
        s += cv.x * av.x + cv.y * av.y + cv.z * av.z + cv.w * av.w;
    }
    s += __shfl_down_sync(0xffffffffu, s, 2);
    s += __shfl_down_sync(0xffffffffu, s, 1);

    if (seg == 0) {
        float a = (s > 0.f) ? s : 0.01f * s;
        g_a[(size_t)warp * Hh + h] = a;
        float* addr = &g_amax[(size_t)dst[warp] * Hh + h];
        if (a >= 0.f) atomicMax((int*)addr, __float_as_int(a));
        else          atomicMin((unsigned int*)addr, __float_as_uint(a));
    }
}

// ---------------- exp + denominator -----------------------------------------
__global__ void softmax_norm_kernel(const int* __restrict__ dst) {
    int i = blockIdx.x * blockDim.x + threadIdx.x;
    if (i >= Ee * Hh) return;
    int e = i >> 3, h = i & 7;
    int d = dst[e];
    float ex = __expf(g_a[i] - g_amax[(size_t)d * Hh + h]);
    g_a[i] = ex;
    atomicAdd(&g_den[(size_t)d * Hh + h], ex);
}

// ---------------- weighted segment scatter ----------------------------------
__global__ void scatter_out_kernel(const int* __restrict__ dst,
                                   float* __restrict__ out) {
    int i = blockIdx.x * blockDim.x + threadIdx.x;
    if (i >= Ee * HIDc) return;
    int e = i >> 9, col = i & 511, h = col >> 6;
    int d = dst[e];
    float w = g_a[(size_t)e * Hh + h] / g_den[(size_t)d * Hh + h];
    atomicAdd(out + (size_t)d * HIDc + col, g_h1[i] * w);
}

// ---------------- launch ------------------------------------------------------
extern "C" void kernel_launch(void* const* d_in, const int* in_sizes, int n_in,
                              void* d_out, int out_size)
{
    const float* feat = (const float*)d_in[0];
    const int*   idx  = (const int*)d_in[2];
    const int*   dst  = (const int*)d_in[3];
    const float* Wih  = (const float*)d_in[4];
    const float* Whh  = (const float*)d_in[5];
    const float* bih  = (const float*)d_in[6];
    const float* bhh  = (const float*)d_in[7];
    const float* a1w  = (const float*)d_in[8];
    const float* a2w  = (const float*)d_in[9];
    float* out = (float*)d_out;

    cudaFuncSetAttribute(lstm_mma_kernel,
                         cudaFuncAttributeMaxDynamicSharedMemorySize, DYN_SMEM);

    // grid must cover max(Nn*Dd, 4*HIDc*HIDc) elements = Nn*Dd = 1.28M
    prep_kernel<<<(Nn * Dd + 255) / 256, 256>>>(Wih, Whh, feat);
    init_kernel<<<(Nn * HIDc + 255) / 256, 256>>>(out);

    dim3 lgrid((Ee + BM - 1) / BM, HIDc / BNH);   // 782 x 16
    for (int t = 0; t < Ll; t++)
        lstm_mma_kernel<<<lgrid, 256, DYN_SMEM>>>(idx, bih, bhh, t);

    attn_logits_kernel<<<(Ee * 32 + 255) / 256, 256>>>(feat, idx, dst, a1w, a2w);
    softmax_norm_kernel<<<(Ee * Hh + 255) / 256, 256>>>(dst);
    scatter_out_kernel<<<(Ee * HIDc + 255) / 256, 256>>>(dst, out);
}

// round 11
// speedup vs baseline: 2.0160x; 1.0177x over previous
#include <cuda_runtime.h>
#include <cuda_fp16.h>
#include <math.h>
#include <stdint.h>

// Problem constants (fixed-shape problem)
#define Nn   20000
#define Ee   100000
#define Ll   4
#define Dd   64
#define Hh   8
#define HIDc 512

// mma.sync fp16 LSTM tiling (R10 structure: 128x32, 8 warps, 2 CTAs/SM)
#define BM   128        // edges per CTA
#define BNH  32         // hidden units per CTA -> 128 gate columns
#define BK   32         // K per chunk (32 fp16 = 16 words)
#define LDSW 20         // smem row stride in WORDS (80B: ldmatrix conflict-free)
#define TILE_WORDS (BM * LDSW)                 // 2560
#define STAGE_WORDS (2 * TILE_WORDS)           // A + B = 5120 words
#define NSTAGE 3
#define DYN_SMEM (NSTAGE * STAGE_WORDS * 4)    // 61440 B -> 2 CTAs/SM easily

// ---------------- scratch (device globals; no allocation allowed) ----------
__device__ float  g_h1[(size_t)Ee * HIDc];     // final-step h (fp32, attn/scatter)
__device__ float  g_c [(size_t)Ee * HIDc];     // cell state (fp32)
__device__ __half g_h16a[(size_t)Ee * HIDc];   // h ping (fp16, MMA operand)
__device__ __half g_h16b[(size_t)Ee * HIDc];   // h pong
__device__ float  g_a [(size_t)Ee * Hh];
__device__ float  g_amax[(size_t)Nn * Hh];
__device__ float  g_den [(size_t)Nn * Hh];
// fp16 operand copies
__device__ __half g_Wih_h [4 * HIDc * Dd];          // 2048 x 64
__device__ __half g_Whh_h [(size_t)4 * HIDc * HIDc];// 2048 x 512
__device__ __half g_feat_h[(size_t)Nn * Dd];        // 20000 x 64

// ---------------- helpers ----------------------------------------------------
__device__ __forceinline__ uint32_t smem_u32(const void* p) {
    uint32_t a;
    asm("{ .reg .u64 t; cvta.to.shared.u64 t, %1; cvt.u32.u64 %0, t; }"
        : "=r"(a) : "l"(p));
    return a;
}
static __device__ __forceinline__ void cpa16(uint32_t dst, const void* src) {
    asm volatile("cp.async.cg.shared.global [%0], [%1], 16;" :: "r"(dst), "l"(src));
}
#define CP_COMMIT() asm volatile("cp.async.commit_group;")
#define CP_WAIT1()  asm volatile("cp.async.wait_group 1;")

// warp-collective 4-fragment load (non-transposed)
__device__ __forceinline__ void ldsm4(uint32_t& r0, uint32_t& r1,
                                      uint32_t& r2, uint32_t& r3, uint32_t addr) {
    asm volatile("ldmatrix.sync.aligned.m8n8.x4.shared.b16 {%0,%1,%2,%3}, [%4];"
                 : "=r"(r0), "=r"(r1), "=r"(r2), "=r"(r3) : "r"(addr));
}

// m16n8k16 fp16 inputs, fp32 accumulate.
__device__ __forceinline__ void mma16(float* d, const uint32_t* a,
                                      uint32_t b0, uint32_t b1) {
    asm volatile(
        "mma.sync.aligned.m16n8k16.row.col.f32.f16.f16.f32 "
        "{%0,%1,%2,%3}, {%4,%5,%6,%7}, {%8,%9}, {%0,%1,%2,%3};"
        : "+f"(d[0]), "+f"(d[1]), "+f"(d[2]), "+f"(d[3])
        : "r"(a[0]), "r"(a[1]), "r"(a[2]), "r"(a[3]), "r"(b0), "r"(b1));
}

// ---------------- prep: fp16-round weights + features once -------------------
__global__ void prep_kernel(const float* __restrict__ Wih,
                            const float* __restrict__ Whh,
                            const float* __restrict__ feat) {
    int i = blockIdx.x * blockDim.x + threadIdx.x;
    if (i < 4 * HIDc * Dd)   g_Wih_h[i]  = __float2half_rn(Wih[i]);
    if (i < 4 * HIDc * HIDc) g_Whh_h[i]  = __float2half_rn(Whh[i]);
    if (i < Nn * Dd)         g_feat_h[i] = __float2half_rn(feat[i]);
}

// ---------------- init -------------------------------------------------------
__global__ void init_kernel(float* __restrict__ out) {
    int i = blockIdx.x * blockDim.x + threadIdx.x;
    if (i < Nn * HIDc) out[i] = 0.f;
    if (i < Nn * Hh) {
        g_amax[i] = __int_as_float(0xFF800000);
        g_den[i]  = 0.f;
    }
}

// ---------------- tensor-core (mma.sync fp16) LSTM step ----------------------
// gates(E x 2048) = x_t @ W_ih^T + h_prev @ W_hh^T (+bias in epilogue).
// CTA: 128 edges x 32 hidden (128 gate cols). K streamed by 32 through a
// 3-stage cp.async ring, one __syncthreads per chunk. Fragment loads via
// ldmatrix.x4 (6 LDSM per kk instead of 24 LDS). 2 CTAs/SM.
__global__ __launch_bounds__(256, 2)
void lstm_mma_kernel(const int*   __restrict__ idx,
                     const float* __restrict__ bih,
                     const float* __restrict__ bhh,
                     int t)
{
    extern __shared__ uint32_t smem[];
    __shared__ int   rows_s[BM];
    __shared__ float bias_s[128];

    const int tid   = threadIdx.x;
    const int wid   = tid >> 5;
    const int lane  = tid & 31;
    const int warpM = wid & 3;        // 0..3 (rows)
    const int warpN = wid >> 2;       // 0..1 (hidden halves)
    const int e0    = blockIdx.x * BM;
    const int nh0   = blockIdx.y * BNH;

    const __half* hprev16 = (t & 1) ? g_h16a : g_h16b;
    __half*       hnext16 = (t & 1) ? g_h16b : g_h16a;
    const bool first = (t == 0);
    const bool last  = (t == Ll - 1);
    const int  NC    = first ? 2 : 18;        // K chunks: 64 feat (+512 hidden)

    if (tid < BM) {
        int e = e0 + tid; if (e >= Ee) e = Ee - 1;
        rows_s[tid] = idx[e * Ll + t];
    }
    if (tid < 128) {   // bias, c = g*32 + hh
        int g = tid >> 5, hh = tid & 31;
        int r = g * HIDc + nh0 + hh;
        bias_s[tid] = bih[r] + bhh[r];
    }
    __syncthreads();   // rows_s ready before first cp.async fill

    // fill-lane mapping: row r, k-half (16 fp16 = 32B = 2x16B each for A and B)
    const int r     = tid & 127;
    const int kh    = tid >> 7;               // 0/1
    const int k0e   = kh * 16;                // fp16-element offset
    const int k0w   = kh * 8;                 // word offset
    const int wrow  = (r >> 5) * HIDc + nh0 + (r & 31);
    const uint32_t smem_base = smem_u32(smem);
    int eA = e0 + r; if (eA >= Ee) eA = Ee - 1;

    auto fill = [&](int kc) {
        const int s = kc % NSTAGE;
        uint32_t abase = smem_base + (uint32_t)(s * STAGE_WORDS + r * LDSW + k0w) * 4u;
        uint32_t bbase = abase + (uint32_t)TILE_WORDS * 4u;
        const __half* ap = (kc < 2)
            ? g_feat_h + (size_t)rows_s[r] * Dd + kc * BK + k0e
            : hprev16  + (size_t)eA * HIDc + (kc - 2) * BK + k0e;
        const __half* bp = (kc < 2)
            ? g_Wih_h + (size_t)wrow * Dd   + kc * BK + k0e
            : g_Whh_h + (size_t)wrow * HIDc + (kc - 2) * BK + k0e;
        cpa16(abase,      ap);
        cpa16(abase + 16, ap + 8);
        cpa16(bbase,      bp);
        cpa16(bbase + 16, bp + 8);
    };

    float acc[2][2][4][4];
#pragma unroll
    for (int mb = 0; mb < 2; mb++)
#pragma unroll
        for (int nb = 0; nb < 2; nb++)
#pragma unroll
            for (int g = 0; g < 4; g++)
#pragma unroll
                for (int v = 0; v < 4; v++) acc[mb][nb][g][v] = 0.f;

    // prologue: fill stages 0 and 1 (NC >= 2 always)
    fill(0); CP_COMMIT();
    fill(1); CP_COMMIT();

    // ldmatrix lane offsets (bytes), invariant across chunks:
    // A x4: lanes 0-15 -> rows arow0 + (lane&15) at kword kk*8;
    //       lanes 16-31 -> same rows at kword kk*8+4.
    const uint32_t a_lane_off =
        ((uint32_t)((warpM * 32 + (lane & 15)) * LDSW + ((lane >> 4) << 2))) * 4u;
    // B x4 (gate pair p: gates 2p,2p+1): lanes 0-7 g=2p k0-7; 8-15 g=2p k8-15;
    //       16-23 g=2p+1 k0-7; 24-31 g=2p+1 k8-15.
    const uint32_t b_lane_off =
        ((uint32_t)(((lane >> 4) * 32 + warpN * 16 + (lane & 7)) * LDSW
                    + (((lane >> 3) & 1) << 2))) * 4u;

    for (int kc = 0; kc < NC; kc++) {
        CP_WAIT1();                 // stage kc resident (<=1 group pending)
        __syncthreads();            // publish stage kc; orders prior compute
        if (kc + 2 < NC) fill(kc + 2);   // slot (kc-1)%3: consumed last iter
        CP_COMMIT();

        const int s = kc % NSTAGE;
        const uint32_t a_stage = smem_base + (uint32_t)(s * STAGE_WORDS) * 4u;
        const uint32_t b_stage = a_stage + (uint32_t)TILE_WORDS * 4u;
#pragma unroll
        for (int kk = 0; kk < 2; kk++) {      // 2 x k16 per 32-chunk
            const uint32_t koff = (uint32_t)(kk * 8) * 4u;
            uint32_t afr[2][4];
            ldsm4(afr[0][0], afr[0][1], afr[0][2], afr[0][3],
                  a_stage + koff + a_lane_off);
            ldsm4(afr[1][0], afr[1][1], afr[1][2], afr[1][3],
                  a_stage + koff + a_lane_off + (uint32_t)(16 * LDSW) * 4u);
#pragma unroll
            for (int nb = 0; nb < 2; nb++) {
                const uint32_t bnb = b_stage + koff + b_lane_off
                                   + (uint32_t)(nb * 8 * LDSW) * 4u;
#pragma unroll
                for (int p = 0; p < 2; p++) {  // gate pairs (0,1) and (2,3)
                    uint32_t q0, q1, q2, q3;
                    ldsm4(q0, q1, q2, q3, bnb + (uint32_t)(p * 64 * LDSW) * 4u);
                    mma16(acc[0][nb][2 * p],     afr[0], q0, q1);
                    mma16(acc[1][nb][2 * p],     afr[1], q0, q1);
                    mma16(acc[0][nb][2 * p + 1], afr[0], q2, q3);
                    mma16(acc[1][nb][2 * p + 1], afr[1], q2, q3);
                }
            }
        }
    }

    // ---- epilogue: LSTM cell from accumulators ------------------------------
#pragma unroll
    for (int mb = 0; mb < 2; mb++) {
#pragma unroll
        for (int rh = 0; rh < 2; rh++) {
            int e = e0 + warpM * 32 + mb * 16 + (lane >> 2) + rh * 8;
            if (e >= Ee) continue;
            float*  cp   = g_c     + (size_t)e * HIDc + nh0;
            __half* hp16 = hnext16 + (size_t)e * HIDc + nh0;
            float*  hp32 = g_h1    + (size_t)e * HIDc + nh0;
#pragma unroll
            for (int nb = 0; nb < 2; nb++) {
                int hh = warpN * 16 + nb * 8 + (lane & 3) * 2;
                float2 cold = make_float2(0.f, 0.f);
                if (!first) cold = *(const float2*)(cp + hh);
                float cv[2], hv[2];
#pragma unroll
                for (int v = 0; v < 2; v++) {
                    int ci = rh * 2 + v;
                    float gi = acc[mb][nb][0][ci] + bias_s[      hh + v];
                    float gf = acc[mb][nb][1][ci] + bias_s[ 32 + hh + v];
                    float gg = acc[mb][nb][2][ci] + bias_s[ 64 + hh + v];
                    float go = acc[mb][nb][3][ci] + bias_s[ 96 + hh + v];
                    float si = 1.f / (1.f + __expf(-gi));
                    float sf = 1.f / (1.f + __expf(-gf));
                    float tg = tanhf(gg);
                    float so = 1.f / (1.f + __expf(-go));
                    float co = v ? cold.y : cold.x;
                    float cn = sf * co + si * tg;
                    cv[v] = cn;
                    hv[v] = so * tanhf(cn);
                }
                *(float2*)(cp + hh) = make_float2(cv[0], cv[1]);
                // fp16 h for next step's MMA A operand
                *(__half2*)(hp16 + hh) = __floats2half2_rn(hv[0], hv[1]);
                // fp32 h only needed after the last step (attention/scatter)
                if (last) *(float2*)(hp32 + hh) = make_float2(hv[0], hv[1]);
            }
        }
    }
}

// ---------------- attention logits + segment max (warp per edge) -----------
__global__ void attn_logits_kernel(const float* __restrict__ feat,
                                   const int*   __restrict__ idx,
                                   const int*   __restrict__ dst,
                                   const float* __restrict__ attn1w,
                                   const float* __restrict__ attn2)
{
    int warp = (blockIdx.x * blockDim.x + threadIdx.x) >> 5;
    int lane = threadIdx.x & 31;
    if (warp >= Ee) return;
    const float* hlast = g_h1;

    int h   = lane >> 2;
    int seg = lane & 3;

    const float* eft = hlast + (size_t)warp * HIDc + h * Dd;
    const float* w2  = attn2  + h * Dd;
    int cidx = idx[warp * Ll + (Ll - 1)];
    const float* ctr = feat + (size_t)cidx * Dd;
    const float* w1  = attn1w + h * Dd;

    float s = 0.f;
#pragma unroll
    for (int q = 0; q < 4; q++) {
        int o = seg * 16 + q * 4;
        float4 ev = *(const float4*)(eft + o);
        float4 wv = *(const float4*)(w2 + o);
        float4 cv = *(const float4*)(ctr + o);
        float4 av = *(const float4*)(w1 + o);
        s += ev.x * wv.x + ev.y * wv.y + ev.z * wv.z + ev.w * wv.w;
        s += cv.x * av.x + cv.y * av.y + cv.z * av.z + cv.w * av.w;
    }
    s += __shfl_down_sync(0xffffffffu, s, 2);
    s += __shfl_down_sync(0xffffffffu, s, 1);

    if (seg == 0) {
        float a = (s > 0.f) ? s : 0.01f * s;
        g_a[(size_t)warp * Hh + h] = a;
        float* addr = &g_amax[(size_t)dst[warp] * Hh + h];
        if (a >= 0.f) atomicMax((int*)addr, __float_as_int(a));
        else          atomicMin((unsigned int*)addr, __float_as_uint(a));
    }
}

// ---------------- exp + denominator -----------------------------------------
__global__ void softmax_norm_kernel(const int* __restrict__ dst) {
    int i = blockIdx.x * blockDim.x + threadIdx.x;
    if (i >= Ee * Hh) return;
    int e = i >> 3, h = i & 7;
    int d = dst[e];
    float ex = __expf(g_a[i] - g_amax[(size_t)d * Hh + h]);
    g_a[i] = ex;
    atomicAdd(&g_den[(size_t)d * Hh + h], ex);
}

// ---------------- weighted segment scatter ----------------------------------
__global__ void scatter_out_kernel(const int* __restrict__ dst,
                                   float* __restrict__ out) {
    int i = blockIdx.x * blockDim.x + threadIdx.x;
    if (i >= Ee * HIDc) return;
    int e = i >> 9, col = i & 511, h = col >> 6;
    int d = dst[e];
    float w = g_a[(size_t)e * Hh + h] / g_den[(size_t)d * Hh + h];
    atomicAdd(out + (size_t)d * HIDc + col, g_h1[i] * w);
}

// ---------------- launch ------------------------------------------------------
extern "C" void kernel_launch(void* const* d_in, const int* in_sizes, int n_in,
                              void* d_out, int out_size)
{
    const float* feat = (const float*)d_in[0];
    const int*   idx  = (const int*)d_in[2];
    const int*   dst  = (const int*)d_in[3];
    const float* Wih  = (const float*)d_in[4];
    const float* Whh  = (const float*)d_in[5];
    const float* bih  = (const float*)d_in[6];
    const float* bhh  = (const float*)d_in[7];
    const float* a1w  = (const float*)d_in[8];
    const float* a2w  = (const float*)d_in[9];
    float* out = (float*)d_out;

    cudaFuncSetAttribute(lstm_mma_kernel,
                         cudaFuncAttributeMaxDynamicSharedMemorySize, DYN_SMEM);

    // grid must cover max(Nn*Dd, 4*HIDc*HIDc) elements = Nn*Dd = 1.28M
    prep_kernel<<<(Nn * Dd + 255) / 256, 256>>>(Wih, Whh, feat);
    init_kernel<<<(Nn * HIDc + 255) / 256, 256>>>(out);

    dim3 lgrid((Ee + BM - 1) / BM, HIDc / BNH);   // 782 x 16
    for (int t = 0; t < Ll; t++)
        lstm_mma_kernel<<<lgrid, 256, DYN_SMEM>>>(idx, bih, bhh, t);

    attn_logits_kernel<<<(Ee * 32 + 255) / 256, 256>>>(feat, idx, dst, a1w, a2w);
    softmax_norm_kernel<<<(Ee * Hh + 255) / 256, 256>>>(dst);
    scatter_out_kernel<<<(Ee * HIDc + 255) / 256, 256>>>(dst, out);
}

// round 12
// speedup vs baseline: 2.1786x; 1.0806x over previous
#include <cuda_runtime.h>
#include <cuda_fp16.h>
#include <math.h>
#include <stdint.h>

// Problem constants (fixed-shape problem)
#define Nn   20000
#define Ee   100000
#define Ll   4
#define Dd   64
#define Hh   8
#define HIDc 512

// mma.sync fp16 LSTM tiling: 128x32, 16 warps (8M x 2N), 2 CTAs/SM
#define BM   128        // edges per CTA
#define BNH  32         // hidden units per CTA -> 128 gate columns
#define BK   32         // K per chunk (32 fp16 = 16 words)
#define LDSW 20         // smem row stride in WORDS (80B: ldmatrix conflict-free)
#define TILE_WORDS (BM * LDSW)                 // 2560
#define STAGE_WORDS (2 * TILE_WORDS)           // A + B = 5120 words
#define NSTAGE 3
#define DYN_SMEM (NSTAGE * STAGE_WORDS * 4)    // 61440 B -> 2 CTAs/SM easily

// ---------------- scratch (device globals; no allocation allowed) ----------
__device__ float  g_h1[(size_t)Ee * HIDc];     // final-step h (fp32, attn/scatter)
__device__ float  g_c [(size_t)Ee * HIDc];     // cell state (fp32)
__device__ __half g_h16a[(size_t)Ee * HIDc];   // h ping (fp16, MMA operand)
__device__ __half g_h16b[(size_t)Ee * HIDc];   // h pong
__device__ float  g_a [(size_t)Ee * Hh];
__device__ float  g_amax[(size_t)Nn * Hh];
__device__ float  g_den [(size_t)Nn * Hh];
// fp16 operand copies
__device__ __half g_Wih_h [4 * HIDc * Dd];          // 2048 x 64
__device__ __half g_Whh_h [(size_t)4 * HIDc * HIDc];// 2048 x 512
__device__ __half g_feat_h[(size_t)Nn * Dd];        // 20000 x 64

// ---------------- helpers ----------------------------------------------------
__device__ __forceinline__ uint32_t smem_u32(const void* p) {
    uint32_t a;
    asm("{ .reg .u64 t; cvta.to.shared.u64 t, %1; cvt.u32.u64 %0, t; }"
        : "=r"(a) : "l"(p));
    return a;
}
static __device__ __forceinline__ void cpa16(uint32_t dst, const void* src) {
    asm volatile("cp.async.cg.shared.global [%0], [%1], 16;" :: "r"(dst), "l"(src));
}
#define CP_COMMIT() asm volatile("cp.async.commit_group;")
#define CP_WAIT1()  asm volatile("cp.async.wait_group 1;")

// warp-collective 4-fragment load (non-transposed)
__device__ __forceinline__ void ldsm4(uint32_t& r0, uint32_t& r1,
                                      uint32_t& r2, uint32_t& r3, uint32_t addr) {
    asm volatile("ldmatrix.sync.aligned.m8n8.x4.shared.b16 {%0,%1,%2,%3}, [%4];"
                 : "=r"(r0), "=r"(r1), "=r"(r2), "=r"(r3) : "r"(addr));
}

// m16n8k16 fp16 inputs, fp32 accumulate.
__device__ __forceinline__ void mma16(float* d, const uint32_t* a,
                                      uint32_t b0, uint32_t b1) {
    asm volatile(
        "mma.sync.aligned.m16n8k16.row.col.f32.f16.f16.f32 "
        "{%0,%1,%2,%3}, {%4,%5,%6,%7}, {%8,%9}, {%0,%1,%2,%3};"
        : "+f"(d[0]), "+f"(d[1]), "+f"(d[2]), "+f"(d[3])
        : "r"(a[0]), "r"(a[1]), "r"(a[2]), "r"(a[3]), "r"(b0), "r"(b1));
}

// ---------------- prep: fp16-round weights + features once -------------------
__global__ void prep_kernel(const float* __restrict__ Wih,
                            const float* __restrict__ Whh,
                            const float* __restrict__ feat) {
    int i = blockIdx.x * blockDim.x + threadIdx.x;
    if (i < 4 * HIDc * Dd)   g_Wih_h[i]  = __float2half_rn(Wih[i]);
    if (i < 4 * HIDc * HIDc) g_Whh_h[i]  = __float2half_rn(Whh[i]);
    if (i < Nn * Dd)         g_feat_h[i] = __float2half_rn(feat[i]);
}

// ---------------- init -------------------------------------------------------
__global__ void init_kernel(float* __restrict__ out) {
    int i = blockIdx.x * blockDim.x + threadIdx.x;
    if (i < Nn * HIDc) out[i] = 0.f;
    if (i < Nn * Hh) {
        g_amax[i] = __int_as_float(0xFF800000);
        g_den[i]  = 0.f;
    }
}

// ---------------- tensor-core (mma.sync fp16) LSTM step ----------------------
// gates(E x 2048) = x_t @ W_ih^T + h_prev @ W_hh^T (+bias in epilogue).
// CTA: 128 edges x 32 hidden (128 gate cols), 512 threads = 16 warps
// (8 along M: 16 rows each; 2 along N: 16 hidden x 4 gates each).
// Warp acc = 32 floats -> <=64 regs -> 2 CTAs/SM = 32 warps resident.
// K streamed by 32 through a 3-stage cp.async ring, one __syncthreads/chunk.
__global__ __launch_bounds__(512, 2)
void lstm_mma_kernel(const int*   __restrict__ idx,
                     const float* __restrict__ bih,
                     const float* __restrict__ bhh,
                     int t)
{
    extern __shared__ uint32_t smem[];
    __shared__ int   rows_s[BM];
    __shared__ float bias_s[128];

    const int tid   = threadIdx.x;
    const int wid   = tid >> 5;
    const int lane  = tid & 31;
    const int warpM = wid & 7;        // 0..7 (16 rows each)
    const int warpN = wid >> 3;       // 0..1 (16 hidden x 4 gates each)
    const int e0    = blockIdx.x * BM;
    const int nh0   = blockIdx.y * BNH;

    const __half* hprev16 = (t & 1) ? g_h16a : g_h16b;
    __half*       hnext16 = (t & 1) ? g_h16b : g_h16a;
    const bool first = (t == 0);
    const bool last  = (t == Ll - 1);
    const int  NC    = first ? 2 : 18;        // K chunks: 64 feat (+512 hidden)

    if (tid < BM) {
        int e = e0 + tid; if (e >= Ee) e = Ee - 1;
        rows_s[tid] = idx[e * Ll + t];
    }
    if (tid < 128) {   // bias, c = g*32 + hh
        int g = tid >> 5, hh = tid & 31;
        int r = g * HIDc + nh0 + hh;
        bias_s[tid] = bih[r] + bhh[r];
    }
    __syncthreads();   // rows_s ready before first cp.async fill

    // fill-lane mapping: 512 threads; row r (0..127), k-quarter kq (0..3),
    // one 16B cp.async for A and one for B per thread.
    const int r     = tid & 127;
    const int kq    = tid >> 7;               // 0..3
    const int k0e   = kq * 8;                 // fp16-element offset
    const int k0w   = kq * 4;                 // word offset
    const int wrow  = (r >> 5) * HIDc + nh0 + (r & 31);
    const uint32_t smem_base = smem_u32(smem);
    int eA = e0 + r; if (eA >= Ee) eA = Ee - 1;

    auto fill = [&](int kc) {
        const int s = kc % NSTAGE;
        uint32_t abase = smem_base + (uint32_t)(s * STAGE_WORDS + r * LDSW + k0w) * 4u;
        uint32_t bbase = abase + (uint32_t)TILE_WORDS * 4u;
        const __half* ap = (kc < 2)
            ? g_feat_h + (size_t)rows_s[r] * Dd + kc * BK + k0e
            : hprev16  + (size_t)eA * HIDc + (kc - 2) * BK + k0e;
        const __half* bp = (kc < 2)
            ? g_Wih_h + (size_t)wrow * Dd   + kc * BK + k0e
            : g_Whh_h + (size_t)wrow * HIDc + (kc - 2) * BK + k0e;
        cpa16(abase, ap);
        cpa16(bbase, bp);
    };

    float acc[2][4][4];       // [nb][gate][frag]
#pragma unroll
    for (int nb = 0; nb < 2; nb++)
#pragma unroll
        for (int g = 0; g < 4; g++)
#pragma unroll
            for (int v = 0; v < 4; v++) acc[nb][g][v] = 0.f;

    // prologue: fill stages 0 and 1 (NC >= 2 always)
    fill(0); CP_COMMIT();
    fill(1); CP_COMMIT();

    // ldmatrix lane offsets (bytes), invariant across chunks:
    // A x4 (m16k16): lanes 0-15 -> rows warpM*16+(lane&15) at kword kk*8;
    //                lanes 16-31 -> same rows at kword kk*8+4.
    const uint32_t a_lane_off =
        ((uint32_t)((warpM * 16 + (lane & 15)) * LDSW + ((lane >> 4) << 2))) * 4u;
    // B x4 (gate pair p: gates 2p,2p+1): lanes 0-7 g=2p k0-7; 8-15 g=2p k8-15;
    //       16-23 g=2p+1 k0-7; 24-31 g=2p+1 k8-15. Col block = warpN*16 + nb*8.
    const uint32_t b_lane_off =
        ((uint32_t)(((lane >> 4) * 32 + warpN * 16 + (lane & 7)) * LDSW
                    + (((lane >> 3) & 1) << 2))) * 4u;

    for (int kc = 0; kc < NC; kc++) {
        CP_WAIT1();                 // stage kc resident (<=1 group pending)
        __syncthreads();            // publish stage kc; orders prior compute
        if (kc + 2 < NC) fill(kc + 2);   // slot (kc-1)%3: consumed last iter
        CP_COMMIT();

        const int s = kc % NSTAGE;
        const uint32_t a_stage = smem_base + (uint32_t)(s * STAGE_WORDS) * 4u;
        const uint32_t b_stage = a_stage + (uint32_t)TILE_WORDS * 4u;
#pragma unroll
        for (int kk = 0; kk < 2; kk++) {      // 2 x k16 per 32-chunk
            const uint32_t koff = (uint32_t)(kk * 8) * 4u;
            uint32_t afr[4];
            ldsm4(afr[0], afr[1], afr[2], afr[3], a_stage + koff + a_lane_off);
#pragma unroll
            for (int nb = 0; nb < 2; nb++) {
                const uint32_t bnb = b_stage + koff + b_lane_off
                                   + (uint32_t)(nb * 8 * LDSW) * 4u;
#pragma unroll
                for (int p = 0; p < 2; p++) {  // gate pairs (0,1) and (2,3)
                    uint32_t q0, q1, q2, q3;
                    ldsm4(q0, q1, q2, q3, bnb + (uint32_t)(p * 64 * LDSW) * 4u);
                    mma16(acc[nb][2 * p],     afr, q0, q1);
                    mma16(acc[nb][2 * p + 1], afr, q2, q3);
                }
            }
        }
    }

    // ---- epilogue: LSTM cell from accumulators ------------------------------
#pragma unroll
    for (int rh = 0; rh < 2; rh++) {
        int e = e0 + warpM * 16 + (lane >> 2) + rh * 8;
        if (e >= Ee) continue;
        float*  cp   = g_c     + (size_t)e * HIDc + nh0;
        __half* hp16 = hnext16 + (size_t)e * HIDc + nh0;
        float*  hp32 = g_h1    + (size_t)e * HIDc + nh0;
#pragma unroll
        for (int nb = 0; nb < 2; nb++) {
            int hh = warpN * 16 + nb * 8 + (lane & 3) * 2;
            float2 cold = make_float2(0.f, 0.f);
            if (!first) cold = *(const float2*)(cp + hh);
            float cv[2], hv[2];
#pragma unroll
            for (int v = 0; v < 2; v++) {
                int ci = rh * 2 + v;
                float gi = acc[nb][0][ci] + bias_s[      hh + v];
                float gf = acc[nb][1][ci] + bias_s[ 32 + hh + v];
                float gg = acc[nb][2][ci] + bias_s[ 64 + hh + v];
                float go = acc[nb][3][ci] + bias_s[ 96 + hh + v];
                float si = 1.f / (1.f + __expf(-gi));
                float sf = 1.f / (1.f + __expf(-gf));
                float tg = tanhf(gg);
                float so = 1.f / (1.f + __expf(-go));
                float co = v ? cold.y : cold.x;
                float cn = sf * co + si * tg;
                cv[v] = cn;
                hv[v] = so * tanhf(cn);
            }
            *(float2*)(cp + hh) = make_float2(cv[0], cv[1]);
            // fp16 h for next step's MMA A operand
            *(__half2*)(hp16 + hh) = __floats2half2_rn(hv[0], hv[1]);
            // fp32 h only needed after the last step (attention/scatter)
            if (last) *(float2*)(hp32 + hh) = make_float2(hv[0], hv[1]);
        }
    }
}

// ---------------- attention logits + segment max (warp per edge) -----------
__global__ void attn_logits_kernel(const float* __restrict__ feat,
                                   const int*   __restrict__ idx,
                                   const int*   __restrict__ dst,
                                   const float* __restrict__ attn1w,
                                   const float* __restrict__ attn2)
{
    int warp = (blockIdx.x * blockDim.x + threadIdx.x) >> 5;
    int lane = threadIdx.x & 31;
    if (warp >= Ee) return;
    const float* hlast = g_h1;

    int h   = lane >> 2;
    int seg = lane & 3;

    const float* eft = hlast + (size_t)warp * HIDc + h * Dd;
    const float* w2  = attn2  + h * Dd;
    int cidx = idx[warp * Ll + (Ll - 1)];
    const float* ctr = feat + (size_t)cidx * Dd;
    const float* w1  = attn1w + h * Dd;

    float s = 0.f;
#pragma unroll
    for (int q = 0; q < 4; q++) {
        int o = seg * 16 + q * 4;
        float4 ev = *(const float4*)(eft + o);
        float4 wv = *(const float4*)(w2 + o);
        float4 cv = *(const float4*)(ctr + o);
        float4 av = *(const float4*)(w1 + o);
        s += ev.x * wv.x + ev.y * wv.y + ev.z * wv.z + ev.w * wv.w;
        s += cv.x * av.x + cv.y * av.y + cv.z * av.z + cv.w * av.w;
    }
    s += __shfl_down_sync(0xffffffffu, s, 2);
    s += __shfl_down_sync(0xffffffffu, s, 1);

    if (seg == 0) {
        float a = (s > 0.f) ? s : 0.01f * s;
        g_a[(size_t)warp * Hh + h] = a;
        float* addr = &g_amax[(size_t)dst[warp] * Hh + h];
        if (a >= 0.f) atomicMax((int*)addr, __float_as_int(a));
        else          atomicMin((unsigned int*)addr, __float_as_uint(a));
    }
}

// ---------------- exp + denominator -----------------------------------------
__global__ void softmax_norm_kernel(const int* __restrict__ dst) {
    int i = blockIdx.x * blockDim.x + threadIdx.x;
    if (i >= Ee * Hh) return;
    int e = i >> 3, h = i & 7;
    int d = dst[e];
    float ex = __expf(g_a[i] - g_amax[(size_t)d * Hh + h]);
    g_a[i] = ex;
    atomicAdd(&g_den[(size_t)d * Hh + h], ex);
}

// ---------------- weighted segment scatter ----------------------------------
__global__ void scatter_out_kernel(const int* __restrict__ dst,
                                   float* __restrict__ out) {
    int i = blockIdx.x * blockDim.x + threadIdx.x;
    if (i >= Ee * HIDc) return;
    int e = i >> 9, col = i & 511, h = col >> 6;
    int d = dst[e];
    float w = g_a[(size_t)e * Hh + h] / g_den[(size_t)d * Hh + h];
    atomicAdd(out + (size_t)d * HIDc + col, g_h1[i] * w);
}

// ---------------- launch ------------------------------------------------------
extern "C" void kernel_launch(void* const* d_in, const int* in_sizes, int n_in,
                              void* d_out, int out_size)
{
    const float* feat = (const float*)d_in[0];
    const int*   idx  = (const int*)d_in[2];
    const int*   dst  = (const int*)d_in[3];
    const float* Wih  = (const float*)d_in[4];
    const float* Whh  = (const float*)d_in[5];
    const float* bih  = (const float*)d_in[6];
    const float* bhh  = (const float*)d_in[7];
    const float* a1w  = (const float*)d_in[8];
    const float* a2w  = (const float*)d_in[9];
    float* out = (float*)d_out;

    cudaFuncSetAttribute(lstm_mma_kernel,
                         cudaFuncAttributeMaxDynamicSharedMemorySize, DYN_SMEM);

    // grid must cover Nn*Dd = 1.28M elements (largest prep target)
    prep_kernel<<<(Nn * Dd + 255) / 256, 256>>>(Wih, Whh, feat);
    init_kernel<<<(Nn * HIDc + 255) / 256, 256>>>(out);

    dim3 lgrid((Ee + BM - 1) / BM, HIDc / BNH);   // 782 x 16
    for (int t = 0; t < Ll; t++)
        lstm_mma_kernel<<<lgrid, 512, DYN_SMEM>>>(idx, bih, bhh, t);

    attn_logits_kernel<<<(Ee * 32 + 255) / 256, 256>>>(feat, idx, dst, a1w, a2w);
    softmax_norm_kernel<<<(Ee * Hh + 255) / 256, 256>>>(dst);
    scatter_out_kernel<<<(Ee * HIDc + 255) / 256, 256>>>(dst, out);
}

// round 13
// speedup vs baseline: 2.5377x; 1.1649x over previous
#include <cuda_runtime.h>
#include <cuda_fp16.h>
#include <math.h>
#include <stdint.h>

// Problem constants (fixed-shape problem)
#define Nn   20000
#define Ee   100000
#define Ll   4
#define Dd   64
#define Hh   8
#define HIDc 512

// Weight-stationary persistent LSTM tiling:
// CTA = 1024 threads (32 warps = 16 M-warps x 2 N-warps), 1 CTA/SM.
// B slice (128 gate cols x 576 k fp16) resident in smem for the whole kernel;
// A streamed 256 edges at a time through a 3-stage cp.async ring.
#define BMP  256        // edges per block-pass
#define BK   32         // K per chunk (32 fp16)
#define LDSW 20         // A ring row stride in words (80B, ldmatrix conflict-free)
#define A_STAGE_WORDS (BMP * LDSW)      // 5120
#define NSTAGE 3
#define BW   292        // B row stride in words (1168B: ldmatrix conflict-free)
#define B_WORDS (128 * BW)              // 37376 words = 149504 B
#define DYN_SMEM ((B_WORDS + NSTAGE * A_STAGE_WORDS) * 4)   // 210944 B
#define NBLK ((Ee + BMP - 1) / BMP)     // 391 edge blocks
#define GRIDX 37                         // 37*16 = 592 CTAs = 4 waves of 148

// ---------------- scratch (device globals; no allocation allowed) ----------
__device__ float  g_h1[(size_t)Ee * HIDc];     // final-step h (fp32, attn/scatter)
__device__ float  g_c [(size_t)Ee * HIDc];     // cell state (fp32)
__device__ __half g_h16a[(size_t)Ee * HIDc];   // h ping (fp16, MMA operand)
__device__ __half g_h16b[(size_t)Ee * HIDc];   // h pong
__device__ float  g_a [(size_t)Ee * Hh];
__device__ float  g_amax[(size_t)Nn * Hh];
__device__ float  g_den [(size_t)Nn * Hh];
// fp16 operand copies
__device__ __half g_Wih_h [4 * HIDc * Dd];          // 2048 x 64
__device__ __half g_Whh_h [(size_t)4 * HIDc * HIDc];// 2048 x 512
__device__ __half g_feat_h[(size_t)Nn * Dd];        // 20000 x 64

// ---------------- helpers ----------------------------------------------------
__device__ __forceinline__ uint32_t smem_u32(const void* p) {
    uint32_t a;
    asm("{ .reg .u64 t; cvta.to.shared.u64 t, %1; cvt.u32.u64 %0, t; }"
        : "=r"(a) : "l"(p));
    return a;
}
static __device__ __forceinline__ void cpa16(uint32_t dst, const void* src) {
    asm volatile("cp.async.cg.shared.global [%0], [%1], 16;" :: "r"(dst), "l"(src));
}
#define CP_COMMIT() asm volatile("cp.async.commit_group;")
#define CP_WAIT1()  asm volatile("cp.async.wait_group 1;")
#define CP_WAIT0()  asm volatile("cp.async.wait_group 0;")

// warp-collective 4-fragment load (non-transposed)
__device__ __forceinline__ void ldsm4(uint32_t& r0, uint32_t& r1,
                                      uint32_t& r2, uint32_t& r3, uint32_t addr) {
    asm volatile("ldmatrix.sync.aligned.m8n8.x4.shared.b16 {%0,%1,%2,%3}, [%4];"
                 : "=r"(r0), "=r"(r1), "=r"(r2), "=r"(r3) : "r"(addr));
}

// m16n8k16 fp16 inputs, fp32 accumulate.
__device__ __forceinline__ void mma16(float* d, const uint32_t* a,
                                      uint32_t b0, uint32_t b1) {
    asm volatile(
        "mma.sync.aligned.m16n8k16.row.col.f32.f16.f16.f32 "
        "{%0,%1,%2,%3}, {%4,%5,%6,%7}, {%8,%9}, {%0,%1,%2,%3};"
        : "+f"(d[0]), "+f"(d[1]), "+f"(d[2]), "+f"(d[3])
        : "r"(a[0]), "r"(a[1]), "r"(a[2]), "r"(a[3]), "r"(b0), "r"(b1));
}

// ---------------- prep: fp16-round weights + features once -------------------
__global__ void prep_kernel(const float* __restrict__ Wih,
                            const float* __restrict__ Whh,
                            const float* __restrict__ feat) {
    int i = blockIdx.x * blockDim.x + threadIdx.x;
    if (i < 4 * HIDc * Dd)   g_Wih_h[i]  = __float2half_rn(Wih[i]);
    if (i < 4 * HIDc * HIDc) g_Whh_h[i]  = __float2half_rn(Whh[i]);
    if (i < Nn * Dd)         g_feat_h[i] = __float2half_rn(feat[i]);
}

// ---------------- init -------------------------------------------------------
__global__ void init_kernel(float* __restrict__ out) {
    int i = blockIdx.x * blockDim.x + threadIdx.x;
    if (i < Nn * HIDc) out[i] = 0.f;
    if (i < Nn * Hh) {
        g_amax[i] = __int_as_float(0xFF800000);
        g_den[i]  = 0.f;
    }
}

// ---------------- weight-stationary persistent LSTM step ---------------------
// gates(E x 2048) = x_t @ W_ih^T + h_prev @ W_hh^T (+bias in epilogue).
// B smem layout: row c (gate col, 0..127; weight row = (c>>5)*512 + nh0 + (c&31)),
// halves 0..63 = Wih k, halves 64..575 = Whh k; row stride 584 halves (1168B).
__global__ __launch_bounds__(1024, 1)
void lstm_mma_kernel(const int*   __restrict__ idx,
                     const float* __restrict__ bih,
                     const float* __restrict__ bhh,
                     int t)
{
    extern __shared__ uint32_t smem[];
    __shared__ int   rows_s[BMP];
    __shared__ float bias_s[128];

    const int tid   = threadIdx.x;
    const int wid   = tid >> 5;
    const int lane  = tid & 31;
    const int warpM = wid & 15;       // 0..15 (16 rows each)
    const int warpN = wid >> 4;       // 0..1  (16 hidden x 4 gates each)
    const int nh0   = blockIdx.y * 32;

    const __half* hprev16 = (t & 1) ? g_h16a : g_h16b;
    __half*       hnext16 = (t & 1) ? g_h16b : g_h16a;
    const bool first = (t == 0);
    const bool last  = (t == Ll - 1);
    const int  NC    = first ? 2 : 18;        // K chunks: 64 feat (+512 hidden)

    const uint32_t b_base = smem_u32(smem);
    const uint32_t a_base = b_base + (uint32_t)B_WORDS * 4u;

    // ---- load B (weights slice) into smem ONCE: 128 rows x 72 16B-chunks ----
    for (int j = tid; j < 128 * 72; j += 1024) {
        int row = j / 72, c = j % 72;
        int wrow = (row >> 5) * HIDc + nh0 + (row & 31);
        uint32_t dst = b_base + (uint32_t)row * 1168u
                     + (uint32_t)(c < 8 ? c * 16 : 128 + (c - 8) * 16);
        const __half* src = (c < 8)
            ? g_Wih_h + (size_t)wrow * Dd   + c * 8
            : g_Whh_h + (size_t)wrow * HIDc + (c - 8) * 8;
        cpa16(dst, src);
    }
    CP_COMMIT();
    if (tid < 128) {   // bias, c = g*32 + hh
        int g = tid >> 5, hh = tid & 31;
        int r = g * HIDc + nh0 + hh;
        bias_s[tid] = bih[r] + bhh[r];
    }
    CP_WAIT0();
    __syncthreads();

    // edge-block range for this CTA (balanced partition of 391 blocks over 37)
    const int eb0 = (blockIdx.x * NBLK) / GRIDX;
    const int eb1 = ((blockIdx.x + 1) * NBLK) / GRIDX;

    // A fill mapping: 1024 threads -> row rA (0..255), k-quarter kq (0..3)
    const int rA = tid >> 2;
    const int kq = tid & 3;

    // ldmatrix lane offsets (bytes), invariant:
    const uint32_t a_lane_off =
        ((uint32_t)((warpM * 16 + (lane & 15)) * LDSW + ((lane >> 4) << 2))) * 4u;
    // B: row = (2p + (lane>>4))*32 + warpN*16 + nb*8 + (lane&7); k-half sel.
    const uint32_t b_lane_base = b_base
        + (uint32_t)((lane >> 4) * 32 + warpN * 16 + (lane & 7)) * 1168u
        + (uint32_t)(((lane >> 3) & 1) << 4);

    for (int eb = eb0; eb < eb1; eb++) {
        const int e0 = eb * BMP;
        if (tid < BMP) {
            int e = e0 + tid; if (e >= Ee) e = Ee - 1;
            rows_s[tid] = idx[e * Ll + t];
        }
        __syncthreads();   // rows_s ready; prior block's ring reads done

        int eA = e0 + rA; if (eA >= Ee) eA = Ee - 1;

        auto fillA = [&](int kc) {
            const int s = kc % NSTAGE;
            uint32_t dst = a_base
                + (uint32_t)(s * A_STAGE_WORDS + rA * LDSW + kq * 4) * 4u;
            const __half* ap = (kc < 2)
                ? g_feat_h + (size_t)rows_s[rA] * Dd + kc * BK + kq * 8
                : hprev16  + (size_t)eA * HIDc + (kc - 2) * BK + kq * 8;
            cpa16(dst, ap);
        };

        float acc[2][4][4];       // [nb][gate][frag]
#pragma unroll
        for (int nb = 0; nb < 2; nb++)
#pragma unroll
            for (int g = 0; g < 4; g++)
#pragma unroll
                for (int v = 0; v < 4; v++) acc[nb][g][v] = 0.f;

        fillA(0); CP_COMMIT();
        fillA(1); CP_COMMIT();

        for (int kc = 0; kc < NC; kc++) {
            CP_WAIT1();               // stage kc resident
            __syncthreads();          // publish stage kc
            if (kc + 2 < NC) fillA(kc + 2);
            CP_COMMIT();

            const int s = kc % NSTAGE;
            const uint32_t a_stage = a_base + (uint32_t)(s * A_STAGE_WORDS) * 4u;
            // B chunk byte base: halves (kc<2 ? kc*32 : 64+(kc-2)*32) * 2
            const uint32_t kbyte = (uint32_t)(kc < 2 ? kc * 64 : 128 + (kc - 2) * 64);
#pragma unroll
            for (int kk = 0; kk < 2; kk++) {      // 2 x k16 per 32-chunk
                const uint32_t koff = (uint32_t)(kk * 32);
                uint32_t afr[4];
                ldsm4(afr[0], afr[1], afr[2], afr[3],
                      a_stage + koff + a_lane_off);
#pragma unroll
                for (int nb = 0; nb < 2; nb++) {
#pragma unroll
                    for (int p = 0; p < 2; p++) {  // gate pairs (0,1),(2,3)
                        uint32_t q0, q1, q2, q3;
                        ldsm4(q0, q1, q2, q3,
                              b_lane_base + (uint32_t)(p * 64 + nb * 8) * 1168u
                                          + kbyte + koff);
                        mma16(acc[nb][2 * p],     afr, q0, q1);
                        mma16(acc[nb][2 * p + 1], afr, q2, q3);
                    }
                }
            }
        }
        __syncthreads();   // all ring reads done before next block's fills

        // ---- epilogue: LSTM cell from accumulators --------------------------
#pragma unroll
        for (int rh = 0; rh < 2; rh++) {
            int e = e0 + warpM * 16 + (lane >> 2) + rh * 8;
            if (e >= Ee) continue;
            float*  cp   = g_c     + (size_t)e * HIDc + nh0;
            __half* hp16 = hnext16 + (size_t)e * HIDc + nh0;
            float*  hp32 = g_h1    + (size_t)e * HIDc + nh0;
#pragma unroll
            for (int nb = 0; nb < 2; nb++) {
                int hh = warpN * 16 + nb * 8 + (lane & 3) * 2;
                float2 cold = make_float2(0.f, 0.f);
                if (!first) cold = *(const float2*)(cp + hh);
                float cv[2], hv[2];
#pragma unroll
                for (int v = 0; v < 2; v++) {
                    int ci = rh * 2 + v;
                    float gi = acc[nb][0][ci] + bias_s[      hh + v];
                    float gf = acc[nb][1][ci] + bias_s[ 32 + hh + v];
                    float gg = acc[nb][2][ci] + bias_s[ 64 + hh + v];
                    float go = acc[nb][3][ci] + bias_s[ 96 + hh + v];
                    float si = 1.f / (1.f + __expf(-gi));
                    float sf = 1.f / (1.f + __expf(-gf));
                    float tg = tanhf(gg);
                    float so = 1.f / (1.f + __expf(-go));
                    float co = v ? cold.y : cold.x;
                    float cn = sf * co + si * tg;
                    cv[v] = cn;
                    hv[v] = so * tanhf(cn);
                }
                *(float2*)(cp + hh) = make_float2(cv[0], cv[1]);
                *(__half2*)(hp16 + hh) = __floats2half2_rn(hv[0], hv[1]);
                if (last) *(float2*)(hp32 + hh) = make_float2(hv[0], hv[1]);
            }
        }
    }
}

// ---------------- attention logits + segment max (warp per edge) -----------
__global__ void attn_logits_kernel(const float* __restrict__ feat,
                                   const int*   __restrict__ idx,
                                   const int*   __restrict__ dst,
                                   const float* __restrict__ attn1w,
                                   const float* __restrict__ attn2)
{
    int warp = (blockIdx.x * blockDim.x + threadIdx.x) >> 5;
    int lane = threadIdx.x & 31;
    if (warp >= Ee) return;
    const float* hlast = g_h1;

    int h   = lane >> 2;
    int seg = lane & 3;

    const float* eft = hlast + (size_t)warp * HIDc + h * Dd;
    const float* w2  = attn2  + h * Dd;
    int cidx = idx[warp * Ll + (Ll - 1)];
    const float* ctr = feat + (size_t)cidx * Dd;
    const float* w1  = attn1w + h * Dd;

    float s = 0.f;
#pragma unroll
    for (int q = 0; q < 4; q++) {
        int o = seg * 16 + q * 4;
        float4 ev = *(const float4*)(eft + o);
        float4 wv = *(const float4*)(w2 + o);
        float4 cv = *(const float4*)(ctr + o);
        float4 av = *(const float4*)(w1 + o);
        s += ev.x * wv.x + ev.y * wv.y + ev.z * wv.z + ev.w * wv.w;
        s += cv.x * av.x + cv.y * av.y + cv.z * av.z + cv.w * av.w;
    }
    s += __shfl_down_sync(0xffffffffu, s, 2);
    s += __shfl_down_sync(0xffffffffu, s, 1);

    if (seg == 0) {
        float a = (s > 0.f) ? s : 0.01f * s;
        g_a[(size_t)warp * Hh + h] = a;
        float* addr = &g_amax[(size_t)dst[warp] * Hh + h];
        if (a >= 0.f) atomicMax((int*)addr, __float_as_int(a));
        else          atomicMin((unsigned int*)addr, __float_as_uint(a));
    }
}

// ---------------- exp + denominator -----------------------------------------
__global__ void softmax_norm_kernel(const int* __restrict__ dst) {
    int i = blockIdx.x * blockDim.x + threadIdx.x;
    if (i >= Ee * Hh) return;
    int e = i >> 3, h = i & 7;
    int d = dst[e];
    float ex = __expf(g_a[i] - g_amax[(size_t)d * Hh + h]);
    g_a[i] = ex;
    atomicAdd(&g_den[(size_t)d * Hh + h], ex);
}

// ---------------- weighted segment scatter ----------------------------------
__global__ void scatter_out_kernel(const int* __restrict__ dst,
                                   float* __restrict__ out) {
    int i = blockIdx.x * blockDim.x + threadIdx.x;
    if (i >= Ee * HIDc) return;
    int e = i >> 9, col = i & 511, h = col >> 6;
    int d = dst[e];
    float w = g_a[(size_t)e * Hh + h] / g_den[(size_t)d * Hh + h];
    atomicAdd(out + (size_t)d * HIDc + col, g_h1[i] * w);
}

// ---------------- launch ------------------------------------------------------
extern "C" void kernel_launch(void* const* d_in, const int* in_sizes, int n_in,
                              void* d_out, int out_size)
{
    const float* feat = (const float*)d_in[0];
    const int*   idx  = (const int*)d_in[2];
    const int*   dst  = (const int*)d_in[3];
    const float* Wih  = (const float*)d_in[4];
    const float* Whh  = (const float*)d_in[5];
    const float* bih  = (const float*)d_in[6];
    const float* bhh  = (const float*)d_in[7];
    const float* a1w  = (const float*)d_in[8];
    const float* a2w  = (const float*)d_in[9];
    float* out = (float*)d_out;

    cudaFuncSetAttribute(lstm_mma_kernel,
                         cudaFuncAttributeMaxDynamicSharedMemorySize, DYN_SMEM);

    prep_kernel<<<(Nn * Dd + 255) / 256, 256>>>(Wih, Whh, feat);
    init_kernel<<<(Nn * HIDc + 255) / 256, 256>>>(out);

    dim3 lgrid(GRIDX, HIDc / 32);   // 37 x 16 = 592 CTAs = 4 full waves
    for (int t = 0; t < Ll; t++)
        lstm_mma_kernel<<<lgrid, 1024, DYN_SMEM>>>(idx, bih, bhh, t);

    attn_logits_kernel<<<(Ee * 32 + 255) / 256, 256>>>(feat, idx, dst, a1w, a2w);
    softmax_norm_kernel<<<(Ee * Hh + 255) / 256, 256>>>(dst);
    scatter_out_kernel<<<(Ee * HIDc + 255) / 256, 256>>>(dst, out);
}

// round 14
// speedup vs baseline: 2.5512x; 1.0053x over previous
#include <cuda_runtime.h>
#include <cuda_fp16.h>
#include <math.h>
#include <stdint.h>

// Problem constants (fixed-shape problem)
#define Nn   20000
#define Ee   100000
#define Ll   4
#define Dd   64
#define Hh   8
#define HIDc 512

// Weight-stationary persistent LSTM tiling:
// CTA = 1024 threads (32 warps = 8 M-warps x 4 N-warps), 1 CTA/SM.
// Warp tile 32 rows x 32 gate cols (8 hidden x 4 gates): B fragments reused
// across both m16 blocks -> 4 ldsm4 per 8 MMAs (was 5).
#define BMP  256        // edges per block-pass
#define BK   32         // K per chunk (32 fp16)
#define LDSW 20         // A ring row stride in words (80B, ldmatrix conflict-free)
#define A_STAGE_WORDS (BMP * LDSW)      // 5120
#define NSTAGE 3
#define B_WORDS (128 * 292)             // 128 rows x 1168B stride
#define DYN_SMEM ((B_WORDS + NSTAGE * A_STAGE_WORDS) * 4)   // 210944 B
#define NBLK ((Ee + BMP - 1) / BMP)     // 391 edge blocks
#define GRIDX 37                         // 37*16 = 592 CTAs = 4 waves of 148

// ---------------- scratch (device globals; no allocation allowed) ----------
__device__ float  g_h1[(size_t)Ee * HIDc];     // final-step h (fp32, attn/scatter)
__device__ float  g_c [(size_t)Ee * HIDc];     // cell state (fp32)
__device__ __half g_h16a[(size_t)Ee * HIDc];   // h ping (fp16, MMA operand)
__device__ __half g_h16b[(size_t)Ee * HIDc];   // h pong
__device__ float  g_a [(size_t)Ee * Hh];
__device__ float  g_amax[(size_t)Nn * Hh];
__device__ float  g_den [(size_t)Nn * Hh];
// fp16 operand copies
__device__ __half g_Wih_h [4 * HIDc * Dd];          // 2048 x 64
__device__ __half g_Whh_h [(size_t)4 * HIDc * HIDc];// 2048 x 512
__device__ __half g_feat_h[(size_t)Nn * Dd];        // 20000 x 64

// ---------------- helpers ----------------------------------------------------
__device__ __forceinline__ uint32_t smem_u32(const void* p) {
    uint32_t a;
    asm("{ .reg .u64 t; cvta.to.shared.u64 t, %1; cvt.u32.u64 %0, t; }"
        : "=r"(a) : "l"(p));
    return a;
}
static __device__ __forceinline__ void cpa16(uint32_t dst, const void* src) {
    asm volatile("cp.async.cg.shared.global [%0], [%1], 16;" :: "r"(dst), "l"(src));
}
#define CP_COMMIT() asm volatile("cp.async.commit_group;")
#define CP_WAIT1()  asm volatile("cp.async.wait_group 1;")
#define CP_WAIT0()  asm volatile("cp.async.wait_group 0;")

// warp-collective 4-fragment load (non-transposed)
__device__ __forceinline__ void ldsm4(uint32_t& r0, uint32_t& r1,
                                      uint32_t& r2, uint32_t& r3, uint32_t addr) {
    asm volatile("ldmatrix.sync.aligned.m8n8.x4.shared.b16 {%0,%1,%2,%3}, [%4];"
                 : "=r"(r0), "=r"(r1), "=r"(r2), "=r"(r3) : "r"(addr));
}

// m16n8k16 fp16 inputs, fp32 accumulate.
__device__ __forceinline__ void mma16(float* d, const uint32_t* a,
                                      uint32_t b0, uint32_t b1) {
    asm volatile(
        "mma.sync.aligned.m16n8k16.row.col.f32.f16.f16.f32 "
        "{%0,%1,%2,%3}, {%4,%5,%6,%7}, {%8,%9}, {%0,%1,%2,%3};"
        : "+f"(d[0]), "+f"(d[1]), "+f"(d[2]), "+f"(d[3])
        : "r"(a[0]), "r"(a[1]), "r"(a[2]), "r"(a[3]), "r"(b0), "r"(b1));
}

// ---------------- prep: fp16-round weights + features once -------------------
__global__ void prep_kernel(const float* __restrict__ Wih,
                            const float* __restrict__ Whh,
                            const float* __restrict__ feat) {
    int i = blockIdx.x * blockDim.x + threadIdx.x;
    if (i < 4 * HIDc * Dd)   g_Wih_h[i]  = __float2half_rn(Wih[i]);
    if (i < 4 * HIDc * HIDc) g_Whh_h[i]  = __float2half_rn(Whh[i]);
    if (i < Nn * Dd)         g_feat_h[i] = __float2half_rn(feat[i]);
}

// ---------------- init -------------------------------------------------------
__global__ void init_kernel(float* __restrict__ out) {
    int i = blockIdx.x * blockDim.x + threadIdx.x;
    if (i < Nn * HIDc) out[i] = 0.f;
    if (i < Nn * Hh) {
        g_amax[i] = __int_as_float(0xFF800000);
        g_den[i]  = 0.f;
    }
}

// ---------------- weight-stationary persistent LSTM step ---------------------
// gates(E x 2048) = x_t @ W_ih^T + h_prev @ W_hh^T (+bias in epilogue).
// B smem layout: row c (gate col, 0..127; weight row = (c>>5)*512 + nh0 + (c&31)),
// halves 0..63 = Wih k, halves 64..575 = Whh k; row stride 584 halves (1168B).
__global__ __launch_bounds__(1024, 1)
void lstm_mma_kernel(const int*   __restrict__ idx,
                     const float* __restrict__ bih,
                     const float* __restrict__ bhh,
                     int t)
{
    extern __shared__ uint32_t smem[];
    __shared__ int   rows_s[BMP];
    __shared__ float bias_s[128];

    const int tid   = threadIdx.x;
    const int wid   = tid >> 5;
    const int lane  = tid & 31;
    const int warpM = wid & 7;        // 0..7  (32 rows each)
    const int warpN = wid >> 3;       // 0..3  (8 hidden x 4 gates each)
    const int nh0   = blockIdx.y * 32;

    const __half* hprev16 = (t & 1) ? g_h16a : g_h16b;
    __half*       hnext16 = (t & 1) ? g_h16b : g_h16a;
    const bool first = (t == 0);
    const bool last  = (t == Ll - 1);
    const int  NC    = first ? 2 : 18;        // K chunks: 64 feat (+512 hidden)

    const uint32_t b_base = smem_u32(smem);
    const uint32_t a_base = b_base + (uint32_t)B_WORDS * 4u;

    // ---- load B (weights slice) into smem ONCE: 128 rows x 72 16B-chunks ----
    for (int j = tid; j < 128 * 72; j += 1024) {
        int row = j / 72, c = j % 72;
        int wrow = (row >> 5) * HIDc + nh0 + (row & 31);
        uint32_t dst = b_base + (uint32_t)row * 1168u
                     + (uint32_t)(c < 8 ? c * 16 : 128 + (c - 8) * 16);
        const __half* src = (c < 8)
            ? g_Wih_h + (size_t)wrow * Dd   + c * 8
            : g_Whh_h + (size_t)wrow * HIDc + (c - 8) * 8;
        cpa16(dst, src);
    }
    CP_COMMIT();
    if (tid < 128) {   // bias, c = g*32 + hh
        int g = tid >> 5, hh = tid & 31;
        int r = g * HIDc + nh0 + hh;
        bias_s[tid] = bih[r] + bhh[r];
    }
    CP_WAIT0();
    __syncthreads();

    // edge-block range for this CTA (balanced partition of 391 blocks over 37)
    const int eb0 = (blockIdx.x * NBLK) / GRIDX;
    const int eb1 = ((blockIdx.x + 1) * NBLK) / GRIDX;

    // A fill mapping: 1024 threads -> row rA (0..255), k-quarter kq (0..3)
    const int rA = tid >> 2;
    const int kq = tid & 3;

    // ldmatrix lane offsets (bytes), invariant:
    // A x4 (m16k16): lanes 0-15 rows +0..15 at kword; 16-31 same rows k+8.
    const uint32_t a_lane_off =
        ((uint32_t)((warpM * 32 + (lane & 15)) * LDSW + ((lane >> 4) << 2))) * 4u;
    // B x4 (gate pair p: gates 2p,2p+1), 8 hidden per warp:
    // lanes 0-7 g=2p k0-7; 8-15 g=2p k8-15; 16-23 g=2p+1 k0-7; 24-31 k8-15.
    const uint32_t b_lane_base = b_base
        + (uint32_t)((lane >> 4) * 32 + warpN * 8 + (lane & 7)) * 1168u
        + (uint32_t)(((lane >> 3) & 1) << 4);

    for (int eb = eb0; eb < eb1; eb++) {
        const int e0 = eb * BMP;
        if (tid < BMP) {
            int e = e0 + tid; if (e >= Ee) e = Ee - 1;
            rows_s[tid] = idx[e * Ll + t];
        }
        __syncthreads();   // rows_s ready; prior block's ring reads done

        int eA = e0 + rA; if (eA >= Ee) eA = Ee - 1;

        auto fillA = [&](int kc) {
            const int s = kc % NSTAGE;
            uint32_t dst = a_base
                + (uint32_t)(s * A_STAGE_WORDS + rA * LDSW + kq * 4) * 4u;
            const __half* ap = (kc < 2)
                ? g_feat_h + (size_t)rows_s[rA] * Dd + kc * BK + kq * 8
                : hprev16  + (size_t)eA * HIDc + (kc - 2) * BK + kq * 8;
            cpa16(dst, ap);
        };

        float acc[2][4][4];       // [mb][gate][frag]
#pragma unroll
        for (int mb = 0; mb < 2; mb++)
#pragma unroll
            for (int g = 0; g < 4; g++)
#pragma unroll
                for (int v = 0; v < 4; v++) acc[mb][g][v] = 0.f;

        fillA(0); CP_COMMIT();
        fillA(1); CP_COMMIT();

        for (int kc = 0; kc < NC; kc++) {
            CP_WAIT1();               // stage kc resident
            __syncthreads();          // publish stage kc
            if (kc + 2 < NC) fillA(kc + 2);
            CP_COMMIT();

            const int s = kc % NSTAGE;
            const uint32_t a_stage = a_base + (uint32_t)(s * A_STAGE_WORDS) * 4u;
            const uint32_t kbyte = (uint32_t)(kc < 2 ? kc * 64 : 128 + (kc - 2) * 64);
#pragma unroll
            for (int kk = 0; kk < 2; kk++) {      // 2 x k16 per 32-chunk
                const uint32_t koff = (uint32_t)(kk * 32);
                uint32_t afr[2][4];
                ldsm4(afr[0][0], afr[0][1], afr[0][2], afr[0][3],
                      a_stage + koff + a_lane_off);
                ldsm4(afr[1][0], afr[1][1], afr[1][2], afr[1][3],
                      a_stage + koff + a_lane_off + (uint32_t)(16 * LDSW) * 4u);
#pragma unroll
                for (int p = 0; p < 2; p++) {  // gate pairs (0,1),(2,3)
                    uint32_t q0, q1, q2, q3;
                    ldsm4(q0, q1, q2, q3,
                          b_lane_base + (uint32_t)(p * 64) * 1168u + kbyte + koff);
                    mma16(acc[0][2 * p],     afr[0], q0, q1);
                    mma16(acc[1][2 * p],     afr[1], q0, q1);
                    mma16(acc[0][2 * p + 1], afr[0], q2, q3);
                    mma16(acc[1][2 * p + 1], afr[1], q2, q3);
                }
            }
        }
        __syncthreads();   // all ring reads done before next block's fills

        // ---- epilogue: LSTM cell from accumulators --------------------------
#pragma unroll
        for (int mb = 0; mb < 2; mb++) {
#pragma unroll
            for (int rh = 0; rh < 2; rh++) {
                int e = e0 + warpM * 32 + mb * 16 + (lane >> 2) + rh * 8;
                if (e >= Ee) continue;
                float*  cp   = g_c     + (size_t)e * HIDc + nh0;
                __half* hp16 = hnext16 + (size_t)e * HIDc + nh0;
                float*  hp32 = g_h1    + (size_t)e * HIDc + nh0;
                int hh = warpN * 8 + (lane & 3) * 2;
                float2 cold = make_float2(0.f, 0.f);
                if (!first) cold = *(const float2*)(cp + hh);
                float cv[2], hv[2];
#pragma unroll
                for (int v = 0; v < 2; v++) {
                    int ci = rh * 2 + v;
                    float gi = acc[mb][0][ci] + bias_s[      hh + v];
                    float gf = acc[mb][1][ci] + bias_s[ 32 + hh + v];
                    float gg = acc[mb][2][ci] + bias_s[ 64 + hh + v];
                    float go = acc[mb][3][ci] + bias_s[ 96 + hh + v];
                    float si = 1.f / (1.f + __expf(-gi));
                    float sf = 1.f / (1.f + __expf(-gf));
                    float tg = tanhf(gg);
                    float so = 1.f / (1.f + __expf(-go));
                    float co = v ? cold.y : cold.x;
                    float cn = sf * co + si * tg;
                    cv[v] = cn;
                    hv[v] = so * tanhf(cn);
                }
                *(float2*)(cp + hh) = make_float2(cv[0], cv[1]);
                *(__half2*)(hp16 + hh) = __floats2half2_rn(hv[0], hv[1]);
                if (last) *(float2*)(hp32 + hh) = make_float2(hv[0], hv[1]);
            }
        }
    }
}

// ---------------- attention logits + segment max (warp per edge) -----------
__global__ void attn_logits_kernel(const float* __restrict__ feat,
                                   const int*   __restrict__ idx,
                                   const int*   __restrict__ dst,
                                   const float* __restrict__ attn1w,
                                   const float* __restrict__ attn2)
{
    int warp = (blockIdx.x * blockDim.x + threadIdx.x) >> 5;
    int lane = threadIdx.x & 31;
    if (warp >= Ee) return;
    const float* hlast = g_h1;

    int h   = lane >> 2;
    int seg = lane & 3;

    const float* eft = hlast + (size_t)warp * HIDc + h * Dd;
    const float* w2  = attn2  + h * Dd;
    int cidx = idx[warp * Ll + (Ll - 1)];
    const float* ctr = feat + (size_t)cidx * Dd;
    const float* w1  = attn1w + h * Dd;

    float s = 0.f;
#pragma unroll
    for (int q = 0; q < 4; q++) {
        int o = seg * 16 + q * 4;
        float4 ev = *(const float4*)(eft + o);
        float4 wv = *(const float4*)(w2 + o);
        float4 cv = *(const float4*)(ctr + o);
        float4 av = *(const float4*)(w1 + o);
        s += ev.x * wv.x + ev.y * wv.y + ev.z * wv.z + ev.w * wv.w;
        s += cv.x * av.x + cv.y * av.y + cv.z * av.z + cv.w * av.w;
    }
    s += __shfl_down_sync(0xffffffffu, s, 2);
    s += __shfl_down_sync(0xffffffffu, s, 1);

    if (seg == 0) {
        float a = (s > 0.f) ? s : 0.01f * s;
        g_a[(size_t)warp * Hh + h] = a;
        float* addr = &g_amax[(size_t)dst[warp] * Hh + h];
        if (a >= 0.f) atomicMax((int*)addr, __float_as_int(a));
        else          atomicMin((unsigned int*)addr, __float_as_uint(a));
    }
}

// ---------------- exp + denominator -----------------------------------------
__global__ void softmax_norm_kernel(const int* __restrict__ dst) {
    int i = blockIdx.x * blockDim.x + threadIdx.x;
    if (i >= Ee * Hh) return;
    int e = i >> 3, h = i & 7;
    int d = dst[e];
    float ex = __expf(g_a[i] - g_amax[(size_t)d * Hh + h]);
    g_a[i] = ex;
    atomicAdd(&g_den[(size_t)d * Hh + h], ex);
}

// ---------------- weighted segment scatter ----------------------------------
__global__ void scatter_out_kernel(const int* __restrict__ dst,
                                   float* __restrict__ out) {
    int i = blockIdx.x * blockDim.x + threadIdx.x;
    if (i >= Ee * HIDc) return;
    int e = i >> 9, col = i & 511, h = col >> 6;
    int d = dst[e];
    float w = g_a[(size_t)e * Hh + h] / g_den[(size_t)d * Hh + h];
    atomicAdd(out + (size_t)d * HIDc + col, g_h1[i] * w);
}

// ---------------- launch ------------------------------------------------------
extern "C" void kernel_launch(void* const* d_in, const int* in_sizes, int n_in,
                              void* d_out, int out_size)
{
    const float* feat = (const float*)d_in[0];
    const int*   idx  = (const int*)d_in[2];
    const int*   dst  = (const int*)d_in[3];
    const float* Wih  = (const float*)d_in[4];
    const float* Whh  = (const float*)d_in[5];
    const float* bih  = (const float*)d_in[6];
    const float* bhh  = (const float*)d_in[7];
    const float* a1w  = (const float*)d_in[8];
    const float* a2w  = (const float*)d_in[9];
    float* out = (float*)d_out;

    cudaFuncSetAttribute(lstm_mma_kernel,
                         cudaFuncAttributeMaxDynamicSharedMemorySize, DYN_SMEM);

    prep_kernel<<<(Nn * Dd + 255) / 256, 256>>>(Wih, Whh, feat);
    init_kernel<<<(Nn * HIDc + 255) / 256, 256>>>(out);

    dim3 lgrid(GRIDX, HIDc / 32);   // 37 x 16 = 592 CTAs = 4 full waves
    for (int t = 0; t < Ll; t++)
        lstm_mma_kernel<<<lgrid, 1024, DYN_SMEM>>>(idx, bih, bhh, t);

    attn_logits_kernel<<<(Ee * 32 + 255) / 256, 256>>>(feat, idx, dst, a1w, a2w);
    softmax_norm_kernel<<<(Ee * Hh + 255) / 256, 256>>>(dst);
    scatter_out_kernel<<<(Ee * HIDc + 255) / 256, 256>>>(dst, out);
}